// round 12
// baseline (speedup 1.0000x reference)
#include <cuda_runtime.h>
#include <cuda_bf16.h>
#include <cuda_fp8.h>
#include <math.h>

#define B_ 8
#define C_ 256
#define NPIX 4096
#define HID_ 680
#define SROW 80   // smem plane row stride (bf16), data starts at col 8

// ---------------- scratch ----------------
__device__ __nv_bfloat16 g_xn[B_*C_*NPIX];
__device__ __nv_bfloat16 g_yn[B_*C_*NPIX];
__device__ __nv_bfloat16 g_q [B_*C_*NPIX];
__device__ __nv_bfloat16 g_k [B_*C_*NPIX];
__device__ __nv_bfloat16 g_v [B_*C_*NPIX];
__device__ __nv_bfloat16 g_ov[B_*C_*NPIX];
__device__ float g_x1[B_*C_*NPIX];
__device__ float g_sumsq_q[B_*C_];
__device__ float g_sumsq_k[B_*C_];
__device__ float g_part[16*64*1024];         // split-K partials [seg][bh][c][d]
__device__ __nv_bfloat16 g_attnb[64*1024];
__device__ __nv_bfloat16 g_t[B_*2*HID_*NPIX];
__device__ __nv_bfloat16 g_h[B_*HID_*NPIX];
__device__ __nv_bfloat16 g_wP[256*256];
__device__ __nv_bfloat16 g_wO[256*680];
__device__ unsigned char g_wI8[1360*256];          // fp8 e4m3, scaled x16
__device__ unsigned char g_xn8[(size_t)B_*NPIX*256]; // fp8 LN2 output, [b][px][ch]

// ---------------- mma helpers ----------------
#define MMA16816(d, a, b0, b1) \
    asm volatile("mma.sync.aligned.m16n8k16.row.col.f32.bf16.bf16.f32 " \
        "{%0,%1,%2,%3},{%4,%5,%6,%7},{%8,%9},{%0,%1,%2,%3};" \
        : "+f"(d[0]),"+f"(d[1]),"+f"(d[2]),"+f"(d[3]) \
        : "r"(a[0]),"r"(a[1]),"r"(a[2]),"r"(a[3]),"r"(b0),"r"(b1))

#define MMAFP8(d, a, b0, b1) \
    asm volatile("mma.sync.aligned.m16n8k32.row.col.f32.e4m3.e4m3.f32 " \
        "{%0,%1,%2,%3},{%4,%5,%6,%7},{%8,%9},{%0,%1,%2,%3};" \
        : "+f"(d[0]),"+f"(d[1]),"+f"(d[2]),"+f"(d[3]) \
        : "r"(a[0]),"r"(a[1]),"r"(a[2]),"r"(a[3]),"r"(b0),"r"(b1))

#define LDSM4(r0,r1,r2,r3,addr) \
    asm volatile("ldmatrix.sync.aligned.m8n8.x4.shared.b16 {%0,%1,%2,%3},[%4];" \
        : "=r"(r0),"=r"(r1),"=r"(r2),"=r"(r3) : "r"(addr))

#define LDSM4T(r0,r1,r2,r3,addr) \
    asm volatile("ldmatrix.sync.aligned.m8n8.x4.trans.shared.b16 {%0,%1,%2,%3},[%4];" \
        : "=r"(r0),"=r"(r1),"=r"(r2),"=r"(r3) : "r"(addr))

#define CP16(dst, src) \
    asm volatile("cp.async.cg.shared.global [%0], [%1], 16;" :: "r"(dst), "l"(src))

#define CP16A(dst, src) \
    asm volatile("cp.async.ca.shared.global [%0], [%1], 16;" :: "r"(dst), "l"(src))

__device__ __forceinline__ unsigned packbf2(float a, float b) {
    __nv_bfloat162 h = __floats2bfloat162_rn(a, b);
    return *reinterpret_cast<unsigned*>(&h);
}

__device__ __forceinline__ unsigned char f2e4m3(float v) {
    return (unsigned char)__nv_cvt_float_to_fp8(v, __NV_SATFINITE, __NV_E4M3);
}

// ---------------- weight convert ----------------
__global__ void k_cvtw(const float* __restrict__ p, const float* __restrict__ wi,
                       const float* __restrict__ wo)
{
    const int NP = 256*256, NI = 1360*256, NO = 256*680;
    for (int i = blockIdx.x*256 + threadIdx.x; i < NP+NI+NO; i += gridDim.x*256) {
        if (i < NP) g_wP[i] = __float2bfloat16(p[i]);
        else if (i < NP+NI) g_wI8[i-NP] = f2e4m3(wi[i-NP] * 16.f);
        else g_wO[i-NP-NI] = __float2bfloat16(wo[i-NP-NI]);
    }
}

// ---------------- K1: LayerNorm x,y (register-cached) ----------------
__global__ void __launch_bounds__(256) k_ln1(
    const float* __restrict__ x, const float* __restrict__ y,
    const float* __restrict__ xw, const float* __restrict__ xb,
    const float* __restrict__ yw, const float* __restrict__ yb)
{
    const int blk = blockIdx.x;
    const int b   = blk >> 7;
    const int pt  = (blk & 127) * 32;
    const int tid = threadIdx.x;
    const int p    = tid & 31;
    const int part = tid >> 5;
    const size_t base = (size_t)b*C_*NPIX + pt + p;

    __shared__ float s_s[8][32], s_q[8][32], s_mu[32], s_is[32];
    float v[32];

    {
        float s = 0.f, sq = 0.f;
        #pragma unroll 8
        for (int j = 0; j < 32; j++) {
            v[j] = x[base + (size_t)(part*32 + j)*NPIX];
            s += v[j]; sq += v[j]*v[j];
        }
        s_s[part][p] = s; s_q[part][p] = sq;
        __syncthreads();
        if (tid < 32) {
            float a = 0.f, c2 = 0.f;
            #pragma unroll
            for (int j = 0; j < 8; j++) { a += s_s[j][tid]; c2 += s_q[j][tid]; }
            float mu = a * (1.f/256.f);
            float var = c2 * (1.f/256.f) - mu*mu;
            s_mu[tid] = mu; s_is[tid] = rsqrtf(var + 1e-5f);
        }
        __syncthreads();
        float mu = s_mu[p], is = s_is[p];
        #pragma unroll 8
        for (int j = 0; j < 32; j++) {
            int c = part*32 + j;
            g_xn[base + (size_t)c*NPIX] = __float2bfloat16((v[j] - mu)*is*xw[c] + xb[c]);
        }
    }
    __syncthreads();
    {
        float s = 0.f, sq = 0.f;
        #pragma unroll 8
        for (int j = 0; j < 32; j++) {
            v[j] = y[base + (size_t)(part*32 + j)*NPIX];
            s += v[j]; sq += v[j]*v[j];
        }
        s_s[part][p] = s; s_q[part][p] = sq;
        __syncthreads();
        if (tid < 32) {
            float a = 0.f, c2 = 0.f;
            #pragma unroll
            for (int j = 0; j < 8; j++) { a += s_s[j][tid]; c2 += s_q[j][tid]; }
            float mu = a * (1.f/256.f);
            float var = c2 * (1.f/256.f) - mu*mu;
            s_mu[tid] = mu; s_is[tid] = rsqrtf(var + 1e-5f);
        }
        __syncthreads();
        float mu = s_mu[p], is = s_is[p];
        #pragma unroll 8
        for (int j = 0; j < 32; j++) {
            int c = part*32 + j;
            g_yn[base + (size_t)c*NPIX] = __float2bfloat16((v[j] - mu)*is*yw[c] + yb[c]);
        }
    }
}

// ---------------- K2: depthwise QKV + sumsq (vectorized) ----------------
__global__ void __launch_bounds__(256) k_qkv(const float* __restrict__ dw)
{
    const int blk = blockIdx.x;
    const int c   = blk & 255;
    const int tid = threadIdx.x;
    __shared__ __align__(16) __nv_bfloat16 sx[66*SROW];
    __shared__ __align__(16) __nv_bfloat16 sy[66*SROW];

    for (int i = tid; i < 1320; i += 256) {
        if (i < 660) *((float4*)sx + i) = make_float4(0,0,0,0);
        else         *((float4*)sy + (i - 660)) = make_float4(0,0,0,0);
    }
    __syncthreads();
    const size_t pbase = (size_t)blk * NPIX;
    #pragma unroll
    for (int g = 0; g < 2; g++) {
        int gi = g*256 + tid;
        int r = gi >> 3, w = (gi & 7) * 8;
        *(float4*)&sx[(r+1)*SROW + 8 + w] = *(const float4*)&g_xn[pbase + r*64 + w];
        *(float4*)&sy[(r+1)*SROW + 8 + w] = *(const float4*)&g_yn[pbase + r*64 + w];
    }
    __syncthreads();

    float wq[9], wk[9], wv[9];
    #pragma unroll
    for (int j = 0; j < 9; j++) {
        wq[j] = dw[c*9 + j];
        wk[j] = dw[(256 + c)*9 + j];
        wv[j] = dw[(512 + c)*9 + j];
    }

    float sqq = 0.f, sqk = 0.f;
    #pragma unroll
    for (int g = 0; g < 2; g++) {
        int gi = g*256 + tid;
        int r = gi >> 3, w = (gi & 7) * 8;
        uint4 qo, ko, vo;
        unsigned* qp = &qo.x; unsigned* kp = &ko.x; unsigned* vp = &vo.x;
        float qv[2], kv[2], vv[2];
        #pragma unroll
        for (int i = 0; i < 8; i++) {
            int s0 = r*SROW + 7 + w + i;
            float q = 0.f, k = 0.f, v = 0.f;
            #pragma unroll
            for (int dy = 0; dy < 3; dy++)
                #pragma unroll
                for (int dx = 0; dx < 3; dx++) {
                    float xv = __bfloat162float(sx[s0 + dy*SROW + dx]);
                    float yv = __bfloat162float(sy[s0 + dy*SROW + dx]);
                    int t = dy*3 + dx;
                    q = fmaf(xv, wq[t], q);
                    k = fmaf(yv, wk[t], k);
                    v = fmaf(yv, wv[t], v);
                }
            sqq += q*q; sqk += k*k;
            qv[i & 1] = q; kv[i & 1] = k; vv[i & 1] = v;
            if (i & 1) {
                qp[i >> 1] = packbf2(qv[0], qv[1]);
                kp[i >> 1] = packbf2(kv[0], kv[1]);
                vp[i >> 1] = packbf2(vv[0], vv[1]);
            }
        }
        *(uint4*)&g_q[pbase + r*64 + w] = qo;
        *(uint4*)&g_k[pbase + r*64 + w] = ko;
        *(uint4*)&g_v[pbase + r*64 + w] = vo;
    }
    #pragma unroll
    for (int off = 16; off; off >>= 1) {
        sqq += __shfl_down_sync(0xffffffffu, sqq, off);
        sqk += __shfl_down_sync(0xffffffffu, sqk, off);
    }
    __shared__ float rq[8], rk[8];
    if ((tid & 31) == 0) { rq[tid >> 5] = sqq; rk[tid >> 5] = sqk; }
    __syncthreads();
    if (tid == 0) {
        float a = 0.f, bqv = 0.f;
        #pragma unroll
        for (int j = 0; j < 8; j++) { a += rq[j]; bqv += rk[j]; }
        g_sumsq_q[blk] = a;
        g_sumsq_k[blk] = bqv;
    }
}

// ---------------- K3: QK^T partials (split-K=16, mma) ----------------
__global__ void __launch_bounds__(256) k_qks()
{
    const int seg = blockIdx.x;
    const int bh  = blockIdx.y;
    const int b = bh >> 3, h = bh & 7;
    const int tid = threadIdx.x, lane = tid & 31, warp = tid >> 5;
    const int gid = lane >> 2, tg = lane & 3;

    __shared__ __align__(16) char smraw[2*2*32*136*2];
    __nv_bfloat16* sQ = (__nv_bfloat16*)smraw;
    __nv_bfloat16* sK = sQ + 2*32*136;
    float* stage = (float*)smraw;
    const unsigned sQu = (unsigned)__cvta_generic_to_shared(sQ);
    const unsigned sKu = (unsigned)__cvta_generic_to_shared(sK);

    const size_t base = ((size_t)b*C_ + h*32) * NPIX;
    const int r  = tid >> 3;
    const int cg = (tid & 7) * 16;

    auto prefetch = [&](int c, int buf) {
        const int n0 = seg*256 + c * 128;
        const __nv_bfloat16* qp = g_q + base + (size_t)r*NPIX + n0 + cg;
        const __nv_bfloat16* kp = g_k + base + (size_t)r*NPIX + n0 + cg;
        unsigned dq = sQu + (buf*32*136 + r*136 + cg) * 2;
        unsigned dk = sKu + (buf*32*136 + r*136 + cg) * 2;
        CP16(dq,      qp);
        CP16(dq + 16, qp + 8);
        CP16(dk,      kp);
        CP16(dk + 16, kp + 8);
        asm volatile("cp.async.commit_group;" ::);
    };

    float acc[2][4][4];
    #pragma unroll
    for (int i = 0; i < 2; i++)
        #pragma unroll
        for (int j = 0; j < 4; j++)
            #pragma unroll
            for (int q = 0; q < 4; q++) acc[i][j][q] = 0.f;

    prefetch(0, 0);
    prefetch(1, 1);

    #pragma unroll
    for (int c = 0; c < 2; c++) {
        const int buf = c;
        if (c == 0) { asm volatile("cp.async.wait_group 1;" ::); }
        else        { asm volatile("cp.async.wait_group 0;" ::); }
        __syncthreads();

        const int col = warp*16 + (lane >> 4)*8;
        unsigned a[2][4];
        #pragma unroll
        for (int mt = 0; mt < 2; mt++) {
            unsigned addr = sQu + (buf*32*136 + (mt*16 + (lane & 15))*136 + col) * 2;
            LDSM4(a[mt][0], a[mt][1], a[mt][2], a[mt][3], addr);
        }
        #pragma unroll
        for (int nt = 0; nt < 2; nt++) {
            unsigned r0, r1, r2, r3;
            unsigned addr = sKu + (buf*32*136 + (nt*16 + (lane & 15))*136 + col) * 2;
            LDSM4(r0, r1, r2, r3, addr);
            MMA16816(acc[0][nt*2],   a[0], r0, r2);
            MMA16816(acc[1][nt*2],   a[1], r0, r2);
            MMA16816(acc[0][nt*2+1], a[0], r1, r3);
            MMA16816(acc[1][nt*2+1], a[1], r1, r3);
        }
        __syncthreads();
    }

    #pragma unroll
    for (int mt = 0; mt < 2; mt++)
        #pragma unroll
        for (int j = 0; j < 4; j++) {
            int c0 = mt*16 + gid, d0 = j*8 + tg*2;
            stage[warp*1056 + c0*33 + d0]       = acc[mt][j][0];
            stage[warp*1056 + c0*33 + d0 + 1]   = acc[mt][j][1];
            stage[warp*1056 + (c0+8)*33 + d0]   = acc[mt][j][2];
            stage[warp*1056 + (c0+8)*33 + d0+1] = acc[mt][j][3];
        }
    __syncthreads();

    const int cc = tid >> 3;
    const int dg = (tid & 7) * 4;
    float4 v = make_float4(0.f, 0.f, 0.f, 0.f);
    #pragma unroll
    for (int w = 0; w < 8; w++) {
        const float* sp = &stage[w*1056 + cc*33 + dg];
        v.x += sp[0]; v.y += sp[1]; v.z += sp[2]; v.w += sp[3];
    }
    *(float4*)&g_part[(((size_t)seg*64 + bh)*32 + cc)*32 + dg] = v;
}

// ---------------- K4: reduce partials + scale + softmax ----------------
__global__ void __launch_bounds__(256) k_soft(const float* __restrict__ temp)
{
    const int bh = blockIdx.x;
    const int b = bh >> 3, h = bh & 7;
    const int tid = threadIdx.x;
    const int cc = tid >> 3;
    const int dg = (tid & 7) * 4;
    const float t = temp[h];

    float v[4] = {0.f, 0.f, 0.f, 0.f};
    #pragma unroll
    for (int sg = 0; sg < 16; sg++) {
        float4 l = *(const float4*)&g_part[(((size_t)sg*64 + bh)*32 + cc)*32 + dg];
        v[0] += l.x; v[1] += l.y; v[2] += l.z; v[3] += l.w;
    }
    float nq = sqrtf(g_sumsq_q[b*C_ + h*32 + cc]);
    float rq = 1.f / fmaxf(nq, 1e-12f);
    float mx = -1e30f;
    #pragma unroll
    for (int j = 0; j < 4; j++) {
        float nk = sqrtf(g_sumsq_k[b*C_ + h*32 + dg + j]);
        v[j] *= rq * (1.f / fmaxf(nk, 1e-12f)) * t;
        mx = fmaxf(mx, v[j]);
    }
    #pragma unroll
    for (int m = 1; m < 8; m <<= 1) mx = fmaxf(mx, __shfl_xor_sync(0xffffffffu, mx, m));
    float sum = 0.f;
    #pragma unroll
    for (int j = 0; j < 4; j++) { v[j] = expf(v[j] - mx); sum += v[j]; }
    #pragma unroll
    for (int m = 1; m < 8; m <<= 1) sum += __shfl_xor_sync(0xffffffffu, sum, m);
    float inv = 1.f / sum;
    __nv_bfloat162* op = reinterpret_cast<__nv_bfloat162*>(&g_attnb[(size_t)bh*1024 + cc*32 + dg]);
    op[0] = __floats2bfloat162_rn(v[0]*inv, v[1]*inv);
    op[1] = __floats2bfloat162_rn(v[2]*inv, v[3]*inv);
}

// ---------------- K5: out = attn @ v (mma) ----------------
__global__ void __launch_bounds__(256) k_av2()
{
    const int seg = blockIdx.x;
    const int bh  = blockIdx.y;
    const int b = bh >> 3, h = bh & 7;
    const int tid = threadIdx.x, lane = tid & 31, warp = tid >> 5;
    const int gid = lane >> 2, tg = lane & 3;

    __shared__ __align__(16) __nv_bfloat16 sA[32*40];
    __shared__ __align__(16) __nv_bfloat16 sV[32*520];
    const unsigned sAu = (unsigned)__cvta_generic_to_shared(&sA[0]);
    const unsigned sVu = (unsigned)__cvta_generic_to_shared(&sV[0]);

    {
        int c0 = tid >> 3, d0 = (tid & 7) * 4;
        const __nv_bfloat162* ap = reinterpret_cast<const __nv_bfloat162*>(
            &g_attnb[(size_t)bh*1024 + c0*32 + d0]);
        __nv_bfloat162* sp = reinterpret_cast<__nv_bfloat162*>(&sA[c0*40 + d0]);
        sp[0] = ap[0]; sp[1] = ap[1];
    }
    const size_t vbase = ((size_t)b*C_ + h*32) * NPIX;
    const int pb0 = seg * 512;
    {
        int r = tid >> 3, cg = (tid & 7) * 64;
        #pragma unroll
        for (int j = 0; j < 8; j++)
            *(float4*)&sV[r*520 + cg + j*8] =
                *(const float4*)&g_v[vbase + (size_t)r*NPIX + pb0 + cg + j*8];
    }
    __syncthreads();

    float acc[2][8][4];
    #pragma unroll
    for (int i = 0; i < 2; i++)
        #pragma unroll
        for (int j = 0; j < 8; j++)
            #pragma unroll
            for (int q = 0; q < 4; q++) acc[i][j][q] = 0.f;

    #pragma unroll
    for (int kt = 0; kt < 2; kt++) {
        unsigned a[2][4];
        #pragma unroll
        for (int mt = 0; mt < 2; mt++) {
            unsigned addr = sAu + ((mt*16 + (lane & 15))*40 + kt*16 + (lane >> 4)*8) * 2;
            LDSM4(a[mt][0], a[mt][1], a[mt][2], a[mt][3], addr);
        }
        #pragma unroll
        for (int ntp = 0; ntp < 4; ntp++) {
            unsigned b0, b1, b2, b3;
            unsigned addr = sVu + ((kt*16 + (lane & 7) + ((lane >> 3) & 1)*8)*520 +
                warp*64 + ntp*16 + (lane >> 4)*8) * 2;
            LDSM4T(b0, b1, b2, b3, addr);
            MMA16816(acc[0][2*ntp],   a[0], b0, b1);
            MMA16816(acc[1][2*ntp],   a[1], b0, b1);
            MMA16816(acc[0][2*ntp+1], a[0], b2, b3);
            MMA16816(acc[1][2*ntp+1], a[1], b2, b3);
        }
    }

    #pragma unroll
    for (int mt = 0; mt < 2; mt++)
        #pragma unroll
        for (int nt = 0; nt < 8; nt++) {
            int row = mt*16 + gid;
            int col = pb0 + warp*64 + nt*8 + tg*2;
            size_t o0 = vbase + (size_t)row*NPIX + col;
            size_t o1 = o0 + (size_t)8*NPIX;
            *(__nv_bfloat162*)&g_ov[o0] = __floats2bfloat162_rn(acc[mt][nt][0], acc[mt][nt][1]);
            *(__nv_bfloat162*)&g_ov[o1] = __floats2bfloat162_rn(acc[mt][nt][2], acc[mt][nt][3]);
        }
}

// ---------------- K6: LN2 -> fp8 into g_xn8 [b][px][ch] ----------------
__global__ void __launch_bounds__(256) k_ln2(const float* __restrict__ w,
                                             const float* __restrict__ bia)
{
    const int blk = blockIdx.x;
    const int b  = blk >> 7;
    const int pt = (blk & 127) * 32;
    const int tid = threadIdx.x;
    const int p = tid & 31;
    const int part = tid >> 5;
    const size_t base = (size_t)b*C_*NPIX + pt + p;

    __shared__ float ss[8][32], qq[8][32], s_mu[32], s_is[32];
    float v[32];
    float s = 0.f, sq = 0.f;
    #pragma unroll 8
    for (int j = 0; j < 32; j++) {
        v[j] = g_x1[base + (size_t)(part*32 + j)*NPIX];
        s += v[j]; sq += v[j]*v[j];
    }
    ss[part][p] = s; qq[part][p] = sq;
    __syncthreads();
    if (tid < 32) {
        float a = 0.f, c2 = 0.f;
        #pragma unroll
        for (int j = 0; j < 8; j++) { a += ss[j][tid]; c2 += qq[j][tid]; }
        float mu = a * (1.f/256.f);
        float var = c2 * (1.f/256.f) - mu*mu;
        s_mu[tid] = mu; s_is[tid] = rsqrtf(var + 1e-5f);
    }
    __syncthreads();
    float mu = s_mu[p], is = s_is[p];
    unsigned char* op = &g_xn8[((size_t)b*NPIX + pt + p)*256 + part*32];
    unsigned word = 0;
    #pragma unroll 8
    for (int j = 0; j < 32; j++) {
        int c = part*32 + j;
        float val = (v[j] - mu)*is*w[c] + bia[c];
        word |= (unsigned)f2e4m3(val) << ((j & 3) * 8);
        if ((j & 3) == 3) { *(unsigned*)(op + (j - 3)) = word; word = 0; }
    }
}

// ---------------- FP8 GEMM (ffn_in): t = (1/16) * W8 @ xn8 ----------------
// W8[1360][256] row-major fp8; xn8[px][256] fp8. Tile 128x128, warp 32x64.
__global__ void __launch_bounds__(256) k_mma1f8()
{
    constexpr int O = 1360, K = 256, NC = 8;
    constexpr int AROW = 48, ASZ = 128*AROW;   // bytes per stage
    constexpr int BSZ = 128*AROW;
    constexpr int NSTG = 5;

    const int b  = blockIdx.z;
    const int bn = blockIdx.x * 128;
    const int bm = blockIdx.y * 128;
    const int tid = threadIdx.x, lane = tid & 31, warp = tid >> 5;
    const int wm = warp >> 1, wn = warp & 1;
    const int gid = lane >> 2, tg = lane & 3;

    __shared__ __align__(16) unsigned char sA[NSTG*ASZ];
    __shared__ __align__(16) unsigned char sB[NSTG*BSZ];
    const unsigned sAu = (unsigned)__cvta_generic_to_shared(sA);
    const unsigned sBu = (unsigned)__cvta_generic_to_shared(sB);

    int arow = bm + (tid >> 1); if (arow > O-1) arow = O-1;
    const unsigned char* Arow = g_wI8 + (size_t)arow * K;
    const unsigned char* Bb = g_xn8 + ((size_t)b*NPIX + bn) * 256;
    const int lrow = tid >> 1, half = (tid & 1) * 16;

    float acc[2][8][4];
    #pragma unroll
    for (int i = 0; i < 2; i++)
        #pragma unroll
        for (int j = 0; j < 8; j++)
            #pragma unroll
            for (int q = 0; q < 4; q++) acc[i][j][q] = 0.f;

    auto load_chunk = [&](int c, int buf) {
        const int k0 = c * 32;
        CP16A(sAu + buf*ASZ + lrow*AROW + half, Arow + k0 + half);
        CP16 (sBu + buf*BSZ + lrow*AROW + half, Bb + (size_t)lrow*256 + k0 + half);
        asm volatile("cp.async.commit_group;" ::);
    };

    load_chunk(0, 0);
    load_chunk(1, 1);
    load_chunk(2, 2);
    load_chunk(3, 3);

    int buf = 0;
    for (int c = 0; c < NC; c++) {
        const int rem = NC - 1 - c;
        if (rem >= 3)      { asm volatile("cp.async.wait_group 3;" ::); }
        else if (rem == 2) { asm volatile("cp.async.wait_group 2;" ::); }
        else if (rem == 1) { asm volatile("cp.async.wait_group 1;" ::); }
        else               { asm volatile("cp.async.wait_group 0;" ::); }
        __syncthreads();
        if (c + 4 < NC) {
            int nb = buf + 4; if (nb >= NSTG) nb -= NSTG;
            load_chunk(c + 4, nb);
        }

        unsigned a[2][4];
        #pragma unroll
        for (int mt = 0; mt < 2; mt++) {
            unsigned addr = sAu + buf*ASZ +
                (wm*32 + mt*16 + (lane & 15))*AROW + (lane >> 4)*16;
            LDSM4(a[mt][0], a[mt][1], a[mt][2], a[mt][3], addr);
        }
        #pragma unroll
        for (int ng = 0; ng < 4; ng++) {
            unsigned r0, r1, r2, r3;
            unsigned addr = sBu + buf*BSZ +
                (wn*64 + ng*16 + (lane & 15))*AROW + (lane >> 4)*16;
            LDSM4(r0, r1, r2, r3, addr);
            MMAFP8(acc[0][2*ng],   a[0], r0, r2);
            MMAFP8(acc[1][2*ng],   a[1], r0, r2);
            MMAFP8(acc[0][2*ng+1], a[0], r1, r3);
            MMAFP8(acc[1][2*ng+1], a[1], r1, r3);
        }
        if (++buf == NSTG) buf = 0;
    }

    const float sc = 1.f/16.f;
    #pragma unroll
    for (int mt = 0; mt < 2; mt++) {
        #pragma unroll
        for (int nt = 0; nt < 8; nt++) {
            int row = bm + wm*32 + mt*16 + gid;
            int col = bn + wn*64 + nt*8 + tg*2;
            float* a4 = acc[mt][nt];
            if (row < 1360) {
                size_t o0 = ((size_t)b*1360 + row)*NPIX + col;
                *(__nv_bfloat162*)&g_t[o0] = __floats2bfloat162_rn(a4[0]*sc, a4[1]*sc);
            }
            if (row + 8 < 1360) {
                size_t o1 = ((size_t)b*1360 + row + 8)*NPIX + col;
                *(__nv_bfloat162*)&g_t[o1] = __floats2bfloat162_rn(a4[2]*sc, a4[3]*sc);
            }
        }
    }
}

// ---------------- tensor-core GEMM (modes 0, 2): K=32, 5-stage ----------------
template<int MODE>
__global__ void __launch_bounds__(256) k_mma(const __nv_bfloat16* __restrict__ Wb,
                                             const __nv_bfloat16* __restrict__ Act,
                                             const float* __restrict__ res,
                                             float* __restrict__ outp)
{
    constexpr int O = 256;
    constexpr int K = (MODE == 2) ? 680 : 256;
    constexpr int NC = (K + 31) / 32;
    constexpr int ASZ = 128*40;
    constexpr int BSZ = 32*136;
    constexpr int NSTG = 5;

    const int b  = blockIdx.z;
    const int bn = blockIdx.x * 128;
    const int bm = blockIdx.y * 128;
    const int tid = threadIdx.x, lane = tid & 31, warp = tid >> 5;
    const int wm = warp >> 1, wn = warp & 1;
    const int gid = lane >> 2, tg = lane & 3;

    __shared__ __align__(16) __nv_bfloat16 sA[NSTG][ASZ];
    __shared__ __align__(16) __nv_bfloat16 sB[NSTG][BSZ];
    const unsigned sAu = (unsigned)__cvta_generic_to_shared(&sA[0][0]);
    const unsigned sBu = (unsigned)__cvta_generic_to_shared(&sB[0][0]);

    const int ar = tid >> 1, ac = (tid & 1) * 16;
    const int bk = tid >> 3, bn8 = (tid & 7) * 16;
    int arow = bm + ar; if (arow > O-1) arow = O-1;
    const __nv_bfloat16* Arow = Wb + (size_t)arow * K;
    const __nv_bfloat16* Bbase = Act + (size_t)b * K * NPIX + bn;

    float acc[2][8][4];
    #pragma unroll
    for (int i = 0; i < 2; i++)
        #pragma unroll
        for (int j = 0; j < 8; j++)
            #pragma unroll
            for (int q = 0; q < 4; q++) acc[i][j][q] = 0.f;

    auto load_chunk = [&](int c, int buf) {
        const int k0 = c * 32;
        #pragma unroll
        for (int j = 0; j < 2; j++) {
            int ko = ac + j*8;
            unsigned dst = sAu + (buf*ASZ + ar*40 + ko) * 2;
            if (k0 + ko < K) { CP16A(dst, Arow + k0 + ko); }
            else *(float4*)(&sA[buf][ar*40 + ko]) = make_float4(0,0,0,0);
        }
        #pragma unroll
        for (int j = 0; j < 2; j++) {
            int no = bn8 + j*8;
            unsigned dst = sBu + (buf*BSZ + bk*136 + no) * 2;
            if (k0 + bk < K) { CP16(dst, Bbase + (size_t)(k0 + bk)*NPIX + no); }
            else *(float4*)(&sB[buf][bk*136 + no]) = make_float4(0,0,0,0);
        }
        asm volatile("cp.async.commit_group;" ::);
    };

    load_chunk(0, 0);
    load_chunk(1, 1);
    load_chunk(2, 2);
    load_chunk(3, 3);

    int buf = 0;
    for (int c = 0; c < NC; c++) {
        const int rem = NC - 1 - c;
        if (rem >= 3)      { asm volatile("cp.async.wait_group 3;" ::); }
        else if (rem == 2) { asm volatile("cp.async.wait_group 2;" ::); }
        else if (rem == 1) { asm volatile("cp.async.wait_group 1;" ::); }
        else               { asm volatile("cp.async.wait_group 0;" ::); }
        __syncthreads();
        if (c + 4 < NC) {
            int nb = buf + 4; if (nb >= NSTG) nb -= NSTG;
            load_chunk(c + 4, nb);
        }

        #pragma unroll
        for (int kt = 0; kt < 2; kt++) {
            unsigned a[2][4];
            #pragma unroll
            for (int mt = 0; mt < 2; mt++) {
                unsigned addr = sAu + (buf*ASZ +
                    (wm*32 + mt*16 + (lane & 15))*40 + kt*16 + (lane >> 4)*8) * 2;
                LDSM4(a[mt][0], a[mt][1], a[mt][2], a[mt][3], addr);
            }
            #pragma unroll
            for (int ntp = 0; ntp < 4; ntp++) {
                unsigned b0, b1, b2, b3;
                unsigned addr = sBu + (buf*BSZ +
                    (kt*16 + (lane & 7) + ((lane >> 3) & 1)*8)*136 +
                    wn*64 + ntp*16 + (lane >> 4)*8) * 2;
                LDSM4T(b0, b1, b2, b3, addr);
                MMA16816(acc[0][2*ntp],   a[0], b0, b1);
                MMA16816(acc[1][2*ntp],   a[1], b0, b1);
                MMA16816(acc[0][2*ntp+1], a[0], b2, b3);
                MMA16816(acc[1][2*ntp+1], a[1], b2, b3);
            }
        }
        if (++buf == NSTG) buf = 0;
    }

    #pragma unroll
    for (int mt = 0; mt < 2; mt++) {
        #pragma unroll
        for (int nt = 0; nt < 8; nt++) {
            int row = bm + wm*32 + mt*16 + gid;
            int col = bn + wn*64 + nt*8 + tg*2;
            float* a4 = acc[mt][nt];
            if (MODE == 0) {
                size_t o0 = ((size_t)b*256 + row)*NPIX + col;
                size_t o1 = o0 + (size_t)8*NPIX;
                float2 r0 = *(const float2*)&res[o0];
                float2 r1 = *(const float2*)&res[o1];
                *(float2*)&g_x1[o0] = make_float2(r0.x + a4[0], r0.y + a4[1]);
                *(float2*)&g_x1[o1] = make_float2(r1.x + a4[2], r1.y + a4[3]);
            } else {
                size_t o0 = ((size_t)b*256 + row)*NPIX + col;
                size_t o1 = o0 + (size_t)8*NPIX;
                float2 r0 = *(const float2*)&g_x1[o0];
                float2 r1 = *(const float2*)&g_x1[o1];
                *(float2*)&outp[o0] = make_float2(r0.x + a4[0], r0.y + a4[1]);
                *(float2*)&outp[o1] = make_float2(r1.x + a4[2], r1.y + a4[3]);
            }
        }
    }
}

// ---------------- K8: depthwise + GELU gate (vectorized) ----------------
__global__ void __launch_bounds__(256) k_gate(const float* __restrict__ dw)
{
    const int blk = blockIdx.x;
    const int b = blk / HID_, i = blk % HID_;
    const int tid = threadIdx.x;
    __shared__ __align__(16) __nv_bfloat16 s1[66*SROW];
    __shared__ __align__(16) __nv_bfloat16 s2[66*SROW];

    for (int j = tid; j < 1320; j += 256) {
        if (j < 660) *((float4*)s1 + j) = make_float4(0,0,0,0);
        else         *((float4*)s2 + (j - 660)) = make_float4(0,0,0,0);
    }
    __syncthreads();
    const size_t base1 = ((size_t)b*2*HID_ + i) * NPIX;
    const size_t base2 = ((size_t)b*2*HID_ + HID_ + i) * NPIX;
    #pragma unroll
    for (int g = 0; g < 2; g++) {
        int gi = g*256 + tid;
        int r = gi >> 3, w = (gi & 7) * 8;
        *(float4*)&s1[(r+1)*SROW + 8 + w] = *(const float4*)&g_t[base1 + r*64 + w];
        *(float4*)&s2[(r+1)*SROW + 8 + w] = *(const float4*)&g_t[base2 + r*64 + w];
    }
    __syncthreads();

    float w1[9], w2[9];
    #pragma unroll
    for (int j = 0; j < 9; j++) {
        w1[j] = dw[i*9 + j];
        w2[j] = dw[(HID_ + i)*9 + j];
    }
    const size_t obase = ((size_t)b*HID_ + i) * NPIX;
    #pragma unroll
    for (int g = 0; g < 2; g++) {
        int gi = g*256 + tid;
        int r = gi >> 3, w = (gi & 7) * 8;
        uint4 ho;
        unsigned* hp = &ho.x;
        float hv[2];
        #pragma unroll
        for (int px = 0; px < 8; px++) {
            int s0 = r*SROW + 7 + w + px;
            float a = 0.f, gg = 0.f;
            #pragma unroll
            for (int dy = 0; dy < 3; dy++)
                #pragma unroll
                for (int dx = 0; dx < 3; dx++) {
                    int t = dy*3 + dx;
                    a  = fmaf(__bfloat162float(s1[s0 + dy*SROW + dx]), w1[t], a);
                    gg = fmaf(__bfloat162float(s2[s0 + dy*SROW + dx]), w2[t], gg);
                }
            float ge = 0.5f * a * (1.f + erff(a * 0.70710678118654752f));
            hv[px & 1] = ge * gg;
            if (px & 1) hp[px >> 1] = packbf2(hv[0], hv[1]);
        }
        *(uint4*)&g_h[obase + r*64 + w] = ho;
    }
}

// ---------------- launch ----------------
extern "C" void kernel_launch(void* const* d_in, const int* in_sizes, int n_in,
                              void* d_out, int out_size)
{
    const float* x        = (const float*)d_in[0];
    const float* y        = (const float*)d_in[1];
    const float* ln1x_w   = (const float*)d_in[2];
    const float* ln1x_b   = (const float*)d_in[3];
    const float* ln1y_w   = (const float*)d_in[4];
    const float* ln1y_b   = (const float*)d_in[5];
    const float* ln2_w    = (const float*)d_in[6];
    const float* ln2_b    = (const float*)d_in[7];
    const float* temp     = (const float*)d_in[8];
    const float* qkv_dw   = (const float*)d_in[9];
    const float* proj_w   = (const float*)d_in[10];
    const float* ffn_in_w = (const float*)d_in[11];
    const float* ffn_dw   = (const float*)d_in[12];
    const float* ffn_out_w= (const float*)d_in[13];
    float* out = (float*)d_out;

    __nv_bfloat16 *wP, *wO;
    cudaGetSymbolAddress((void**)&wP, g_wP);
    cudaGetSymbolAddress((void**)&wO, g_wO);
    __nv_bfloat16 *ov, *hh;
    cudaGetSymbolAddress((void**)&ov, g_ov);
    cudaGetSymbolAddress((void**)&hh, g_h);

    k_cvtw<<<576, 256>>>(proj_w, ffn_in_w, ffn_out_w);
    k_ln1<<<B_*128, 256>>>(x, y, ln1x_w, ln1x_b, ln1y_w, ln1y_b);
    k_qkv<<<B_*C_, 256>>>(qkv_dw);
    k_qks<<<dim3(16, 64), 256>>>();
    k_soft<<<64, 256>>>(temp);
    k_av2<<<dim3(8, 64), 256>>>();
    k_mma<0><<<dim3(32, 2, B_), 256>>>(wP, ov, x, nullptr);
    k_ln2<<<B_*128, 256>>>(ln2_w, ln2_b);
    k_mma1f8<<<dim3(32, 11, B_), 256>>>();
    k_gate<<<B_*HID_, 256>>>(ffn_dw);
    k_mma<2><<<dim3(32, 2, B_), 256>>>(wO, hh, nullptr, out);
}

// round 13
// speedup vs baseline: 1.0600x; 1.0600x over previous
#include <cuda_runtime.h>
#include <cuda_bf16.h>
#include <math.h>

#define B_ 8
#define C_ 256
#define NPIX 4096
#define HID_ 680
#define SROW 80   // smem plane row stride (bf16), data starts at col 8

// ---------------- scratch ----------------
__device__ __nv_bfloat16 g_xn[B_*C_*NPIX];
__device__ __nv_bfloat16 g_yn[B_*C_*NPIX];
__device__ __nv_bfloat16 g_q [B_*C_*NPIX];
__device__ __nv_bfloat16 g_k [B_*C_*NPIX];
__device__ __nv_bfloat16 g_v [B_*C_*NPIX];
__device__ __nv_bfloat16 g_ov[B_*C_*NPIX];
__device__ float g_x1[B_*C_*NPIX];
__device__ float g_sumsq_q[B_*C_];
__device__ float g_sumsq_k[B_*C_];
__device__ float g_part[16*64*1024];         // split-K partials [seg][bh][c][d]
__device__ __nv_bfloat16 g_attnb[64*1024];
__device__ __nv_bfloat16 g_t[B_*2*HID_*NPIX];
__device__ __nv_bfloat16 g_h[B_*HID_*NPIX];
__device__ __nv_bfloat16 g_wP[256*256];
__device__ __nv_bfloat16 g_wI[1360*256];
__device__ __nv_bfloat16 g_wO[256*680];

// ---------------- mma helpers ----------------
#define MMA16816(d, a, b0, b1) \
    asm volatile("mma.sync.aligned.m16n8k16.row.col.f32.bf16.bf16.f32 " \
        "{%0,%1,%2,%3},{%4,%5,%6,%7},{%8,%9},{%0,%1,%2,%3};" \
        : "+f"(d[0]),"+f"(d[1]),"+f"(d[2]),"+f"(d[3]) \
        : "r"(a[0]),"r"(a[1]),"r"(a[2]),"r"(a[3]),"r"(b0),"r"(b1))

#define LDSM4(r0,r1,r2,r3,addr) \
    asm volatile("ldmatrix.sync.aligned.m8n8.x4.shared.b16 {%0,%1,%2,%3},[%4];" \
        : "=r"(r0),"=r"(r1),"=r"(r2),"=r"(r3) : "r"(addr))

#define LDSM4T(r0,r1,r2,r3,addr) \
    asm volatile("ldmatrix.sync.aligned.m8n8.x4.trans.shared.b16 {%0,%1,%2,%3},[%4];" \
        : "=r"(r0),"=r"(r1),"=r"(r2),"=r"(r3) : "r"(addr))

#define CP16(dst, src) \
    asm volatile("cp.async.cg.shared.global [%0], [%1], 16;" :: "r"(dst), "l"(src))

#define CP16A(dst, src) \
    asm volatile("cp.async.ca.shared.global [%0], [%1], 16;" :: "r"(dst), "l"(src))

__device__ __forceinline__ unsigned packbf2(float a, float b) {
    __nv_bfloat162 h = __floats2bfloat162_rn(a, b);
    return *reinterpret_cast<unsigned*>(&h);
}

// ---------------- weight convert ----------------
__global__ void k_cvtw(const float* __restrict__ p, const float* __restrict__ wi,
                       const float* __restrict__ wo)
{
    const int NP = 256*256, NI = 1360*256, NO = 256*680;
    for (int i = blockIdx.x*256 + threadIdx.x; i < NP+NI+NO; i += gridDim.x*256) {
        if (i < NP) g_wP[i] = __float2bfloat16(p[i]);
        else if (i < NP+NI) g_wI[i-NP] = __float2bfloat16(wi[i-NP]);
        else g_wO[i-NP-NI] = __float2bfloat16(wo[i-NP-NI]);
    }
}

// ---------------- K1: LayerNorm x,y (register-cached) ----------------
__global__ void __launch_bounds__(256) k_ln1(
    const float* __restrict__ x, const float* __restrict__ y,
    const float* __restrict__ xw, const float* __restrict__ xb,
    const float* __restrict__ yw, const float* __restrict__ yb)
{
    const int blk = blockIdx.x;
    const int b   = blk >> 7;
    const int pt  = (blk & 127) * 32;
    const int tid = threadIdx.x;
    const int p    = tid & 31;
    const int part = tid >> 5;
    const size_t base = (size_t)b*C_*NPIX + pt + p;

    __shared__ float s_s[8][32], s_q[8][32], s_mu[32], s_is[32];
    float v[32];

    {
        float s = 0.f, sq = 0.f;
        #pragma unroll 8
        for (int j = 0; j < 32; j++) {
            v[j] = x[base + (size_t)(part*32 + j)*NPIX];
            s += v[j]; sq += v[j]*v[j];
        }
        s_s[part][p] = s; s_q[part][p] = sq;
        __syncthreads();
        if (tid < 32) {
            float a = 0.f, c2 = 0.f;
            #pragma unroll
            for (int j = 0; j < 8; j++) { a += s_s[j][tid]; c2 += s_q[j][tid]; }
            float mu = a * (1.f/256.f);
            float var = c2 * (1.f/256.f) - mu*mu;
            s_mu[tid] = mu; s_is[tid] = rsqrtf(var + 1e-5f);
        }
        __syncthreads();
        float mu = s_mu[p], is = s_is[p];
        #pragma unroll 8
        for (int j = 0; j < 32; j++) {
            int c = part*32 + j;
            g_xn[base + (size_t)c*NPIX] = __float2bfloat16((v[j] - mu)*is*xw[c] + xb[c]);
        }
    }
    __syncthreads();
    {
        float s = 0.f, sq = 0.f;
        #pragma unroll 8
        for (int j = 0; j < 32; j++) {
            v[j] = y[base + (size_t)(part*32 + j)*NPIX];
            s += v[j]; sq += v[j]*v[j];
        }
        s_s[part][p] = s; s_q[part][p] = sq;
        __syncthreads();
        if (tid < 32) {
            float a = 0.f, c2 = 0.f;
            #pragma unroll
            for (int j = 0; j < 8; j++) { a += s_s[j][tid]; c2 += s_q[j][tid]; }
            float mu = a * (1.f/256.f);
            float var = c2 * (1.f/256.f) - mu*mu;
            s_mu[tid] = mu; s_is[tid] = rsqrtf(var + 1e-5f);
        }
        __syncthreads();
        float mu = s_mu[p], is = s_is[p];
        #pragma unroll 8
        for (int j = 0; j < 32; j++) {
            int c = part*32 + j;
            g_yn[base + (size_t)c*NPIX] = __float2bfloat16((v[j] - mu)*is*yw[c] + yb[c]);
        }
    }
}

// ---------------- K2: depthwise QKV + sumsq (vectorized) ----------------
__global__ void __launch_bounds__(256) k_qkv(const float* __restrict__ dw)
{
    const int blk = blockIdx.x;
    const int c   = blk & 255;
    const int tid = threadIdx.x;
    __shared__ __align__(16) __nv_bfloat16 sx[66*SROW];
    __shared__ __align__(16) __nv_bfloat16 sy[66*SROW];

    for (int i = tid; i < 1320; i += 256) {
        if (i < 660) *((float4*)sx + i) = make_float4(0,0,0,0);
        else         *((float4*)sy + (i - 660)) = make_float4(0,0,0,0);
    }
    __syncthreads();
    const size_t pbase = (size_t)blk * NPIX;
    #pragma unroll
    for (int g = 0; g < 2; g++) {
        int gi = g*256 + tid;
        int r = gi >> 3, w = (gi & 7) * 8;
        *(float4*)&sx[(r+1)*SROW + 8 + w] = *(const float4*)&g_xn[pbase + r*64 + w];
        *(float4*)&sy[(r+1)*SROW + 8 + w] = *(const float4*)&g_yn[pbase + r*64 + w];
    }
    __syncthreads();

    float wq[9], wk[9], wv[9];
    #pragma unroll
    for (int j = 0; j < 9; j++) {
        wq[j] = dw[c*9 + j];
        wk[j] = dw[(256 + c)*9 + j];
        wv[j] = dw[(512 + c)*9 + j];
    }

    float sqq = 0.f, sqk = 0.f;
    #pragma unroll
    for (int g = 0; g < 2; g++) {
        int gi = g*256 + tid;
        int r = gi >> 3, w = (gi & 7) * 8;
        uint4 qo, ko, vo;
        unsigned* qp = &qo.x; unsigned* kp = &ko.x; unsigned* vp = &vo.x;
        float qv[2], kv[2], vv[2];
        #pragma unroll
        for (int i = 0; i < 8; i++) {
            int s0 = r*SROW + 7 + w + i;
            float q = 0.f, k = 0.f, v = 0.f;
            #pragma unroll
            for (int dy = 0; dy < 3; dy++)
                #pragma unroll
                for (int dx = 0; dx < 3; dx++) {
                    float xv = __bfloat162float(sx[s0 + dy*SROW + dx]);
                    float yv = __bfloat162float(sy[s0 + dy*SROW + dx]);
                    int t = dy*3 + dx;
                    q = fmaf(xv, wq[t], q);
                    k = fmaf(yv, wk[t], k);
                    v = fmaf(yv, wv[t], v);
                }
            sqq += q*q; sqk += k*k;
            qv[i & 1] = q; kv[i & 1] = k; vv[i & 1] = v;
            if (i & 1) {
                qp[i >> 1] = packbf2(qv[0], qv[1]);
                kp[i >> 1] = packbf2(kv[0], kv[1]);
                vp[i >> 1] = packbf2(vv[0], vv[1]);
            }
        }
        *(uint4*)&g_q[pbase + r*64 + w] = qo;
        *(uint4*)&g_k[pbase + r*64 + w] = ko;
        *(uint4*)&g_v[pbase + r*64 + w] = vo;
    }
    #pragma unroll
    for (int off = 16; off; off >>= 1) {
        sqq += __shfl_down_sync(0xffffffffu, sqq, off);
        sqk += __shfl_down_sync(0xffffffffu, sqk, off);
    }
    __shared__ float rq[8], rk[8];
    if ((tid & 31) == 0) { rq[tid >> 5] = sqq; rk[tid >> 5] = sqk; }
    __syncthreads();
    if (tid == 0) {
        float a = 0.f, bqv = 0.f;
        #pragma unroll
        for (int j = 0; j < 8; j++) { a += rq[j]; bqv += rk[j]; }
        g_sumsq_q[blk] = a;
        g_sumsq_k[blk] = bqv;
    }
}

// ---------------- K3: QK^T partials (split-K=16, mma) ----------------
__global__ void __launch_bounds__(256) k_qks()
{
    const int seg = blockIdx.x;   // 0..15 (256 pixels each)
    const int bh  = blockIdx.y;   // 0..63
    const int b = bh >> 3, h = bh & 7;
    const int tid = threadIdx.x, lane = tid & 31, warp = tid >> 5;
    const int gid = lane >> 2, tg = lane & 3;

    __shared__ __align__(16) char smraw[2*2*32*136*2];
    __nv_bfloat16* sQ = (__nv_bfloat16*)smraw;
    __nv_bfloat16* sK = sQ + 2*32*136;
    float* stage = (float*)smraw;
    const unsigned sQu = (unsigned)__cvta_generic_to_shared(sQ);
    const unsigned sKu = (unsigned)__cvta_generic_to_shared(sK);

    const size_t base = ((size_t)b*C_ + h*32) * NPIX;
    const int r  = tid >> 3;
    const int cg = (tid & 7) * 16;

    auto prefetch = [&](int c, int buf) {
        const int n0 = seg*256 + c * 128;
        const __nv_bfloat16* qp = g_q + base + (size_t)r*NPIX + n0 + cg;
        const __nv_bfloat16* kp = g_k + base + (size_t)r*NPIX + n0 + cg;
        unsigned dq = sQu + (buf*32*136 + r*136 + cg) * 2;
        unsigned dk = sKu + (buf*32*136 + r*136 + cg) * 2;
        CP16(dq,      qp);
        CP16(dq + 16, qp + 8);
        CP16(dk,      kp);
        CP16(dk + 16, kp + 8);
        asm volatile("cp.async.commit_group;" ::);
    };

    float acc[2][4][4];
    #pragma unroll
    for (int i = 0; i < 2; i++)
        #pragma unroll
        for (int j = 0; j < 4; j++)
            #pragma unroll
            for (int q = 0; q < 4; q++) acc[i][j][q] = 0.f;

    prefetch(0, 0);
    prefetch(1, 1);

    #pragma unroll
    for (int c = 0; c < 2; c++) {
        const int buf = c;
        if (c == 0) { asm volatile("cp.async.wait_group 1;" ::); }
        else        { asm volatile("cp.async.wait_group 0;" ::); }
        __syncthreads();

        const int col = warp*16 + (lane >> 4)*8;
        unsigned a[2][4];
        #pragma unroll
        for (int mt = 0; mt < 2; mt++) {
            unsigned addr = sQu + (buf*32*136 + (mt*16 + (lane & 15))*136 + col) * 2;
            LDSM4(a[mt][0], a[mt][1], a[mt][2], a[mt][3], addr);
        }
        #pragma unroll
        for (int nt = 0; nt < 2; nt++) {
            unsigned r0, r1, r2, r3;
            unsigned addr = sKu + (buf*32*136 + (nt*16 + (lane & 15))*136 + col) * 2;
            LDSM4(r0, r1, r2, r3, addr);
            MMA16816(acc[0][nt*2],   a[0], r0, r2);
            MMA16816(acc[1][nt*2],   a[1], r0, r2);
            MMA16816(acc[0][nt*2+1], a[0], r1, r3);
            MMA16816(acc[1][nt*2+1], a[1], r1, r3);
        }
        __syncthreads();
    }

    #pragma unroll
    for (int mt = 0; mt < 2; mt++)
        #pragma unroll
        for (int j = 0; j < 4; j++) {
            int c0 = mt*16 + gid, d0 = j*8 + tg*2;
            stage[warp*1056 + c0*33 + d0]       = acc[mt][j][0];
            stage[warp*1056 + c0*33 + d0 + 1]   = acc[mt][j][1];
            stage[warp*1056 + (c0+8)*33 + d0]   = acc[mt][j][2];
            stage[warp*1056 + (c0+8)*33 + d0+1] = acc[mt][j][3];
        }
    __syncthreads();

    const int cc = tid >> 3;
    const int dg = (tid & 7) * 4;
    float4 v = make_float4(0.f, 0.f, 0.f, 0.f);
    #pragma unroll
    for (int w = 0; w < 8; w++) {
        const float* sp = &stage[w*1056 + cc*33 + dg];
        v.x += sp[0]; v.y += sp[1]; v.z += sp[2]; v.w += sp[3];
    }
    *(float4*)&g_part[(((size_t)seg*64 + bh)*32 + cc)*32 + dg] = v;
}

// ---------------- K4: reduce partials + scale + softmax ----------------
__global__ void __launch_bounds__(256) k_soft(const float* __restrict__ temp)
{
    const int bh = blockIdx.x;
    const int b = bh >> 3, h = bh & 7;
    const int tid = threadIdx.x;
    const int cc = tid >> 3;
    const int dg = (tid & 7) * 4;
    const float t = temp[h];

    float v[4] = {0.f, 0.f, 0.f, 0.f};
    #pragma unroll
    for (int sg = 0; sg < 16; sg++) {
        float4 l = *(const float4*)&g_part[(((size_t)sg*64 + bh)*32 + cc)*32 + dg];
        v[0] += l.x; v[1] += l.y; v[2] += l.z; v[3] += l.w;
    }
    float nq = sqrtf(g_sumsq_q[b*C_ + h*32 + cc]);
    float rq = 1.f / fmaxf(nq, 1e-12f);
    float mx = -1e30f;
    #pragma unroll
    for (int j = 0; j < 4; j++) {
        float nk = sqrtf(g_sumsq_k[b*C_ + h*32 + dg + j]);
        v[j] *= rq * (1.f / fmaxf(nk, 1e-12f)) * t;
        mx = fmaxf(mx, v[j]);
    }
    #pragma unroll
    for (int m = 1; m < 8; m <<= 1) mx = fmaxf(mx, __shfl_xor_sync(0xffffffffu, mx, m));
    float sum = 0.f;
    #pragma unroll
    for (int j = 0; j < 4; j++) { v[j] = expf(v[j] - mx); sum += v[j]; }
    #pragma unroll
    for (int m = 1; m < 8; m <<= 1) sum += __shfl_xor_sync(0xffffffffu, sum, m);
    float inv = 1.f / sum;
    __nv_bfloat162* op = reinterpret_cast<__nv_bfloat162*>(&g_attnb[(size_t)bh*1024 + cc*32 + dg]);
    op[0] = __floats2bfloat162_rn(v[0]*inv, v[1]*inv);
    op[1] = __floats2bfloat162_rn(v[2]*inv, v[3]*inv);
}

// ---------------- K5: out = attn @ v (mma) ----------------
__global__ void __launch_bounds__(256) k_av2()
{
    const int seg = blockIdx.x;
    const int bh  = blockIdx.y;
    const int b = bh >> 3, h = bh & 7;
    const int tid = threadIdx.x, lane = tid & 31, warp = tid >> 5;
    const int gid = lane >> 2, tg = lane & 3;

    __shared__ __align__(16) __nv_bfloat16 sA[32*40];
    __shared__ __align__(16) __nv_bfloat16 sV[32*520];
    const unsigned sAu = (unsigned)__cvta_generic_to_shared(&sA[0]);
    const unsigned sVu = (unsigned)__cvta_generic_to_shared(&sV[0]);

    {
        int c0 = tid >> 3, d0 = (tid & 7) * 4;
        const __nv_bfloat162* ap = reinterpret_cast<const __nv_bfloat162*>(
            &g_attnb[(size_t)bh*1024 + c0*32 + d0]);
        __nv_bfloat162* sp = reinterpret_cast<__nv_bfloat162*>(&sA[c0*40 + d0]);
        sp[0] = ap[0]; sp[1] = ap[1];
    }
    const size_t vbase = ((size_t)b*C_ + h*32) * NPIX;
    const int pb0 = seg * 512;
    {
        int r = tid >> 3, cg = (tid & 7) * 64;
        #pragma unroll
        for (int j = 0; j < 8; j++)
            *(float4*)&sV[r*520 + cg + j*8] =
                *(const float4*)&g_v[vbase + (size_t)r*NPIX + pb0 + cg + j*8];
    }
    __syncthreads();

    float acc[2][8][4];
    #pragma unroll
    for (int i = 0; i < 2; i++)
        #pragma unroll
        for (int j = 0; j < 8; j++)
            #pragma unroll
            for (int q = 0; q < 4; q++) acc[i][j][q] = 0.f;

    #pragma unroll
    for (int kt = 0; kt < 2; kt++) {
        unsigned a[2][4];
        #pragma unroll
        for (int mt = 0; mt < 2; mt++) {
            unsigned addr = sAu + ((mt*16 + (lane & 15))*40 + kt*16 + (lane >> 4)*8) * 2;
            LDSM4(a[mt][0], a[mt][1], a[mt][2], a[mt][3], addr);
        }
        #pragma unroll
        for (int ntp = 0; ntp < 4; ntp++) {
            unsigned b0, b1, b2, b3;
            unsigned addr = sVu + ((kt*16 + (lane & 7) + ((lane >> 3) & 1)*8)*520 +
                warp*64 + ntp*16 + (lane >> 4)*8) * 2;
            LDSM4T(b0, b1, b2, b3, addr);
            MMA16816(acc[0][2*ntp],   a[0], b0, b1);
            MMA16816(acc[1][2*ntp],   a[1], b0, b1);
            MMA16816(acc[0][2*ntp+1], a[0], b2, b3);
            MMA16816(acc[1][2*ntp+1], a[1], b2, b3);
        }
    }

    #pragma unroll
    for (int mt = 0; mt < 2; mt++)
        #pragma unroll
        for (int nt = 0; nt < 8; nt++) {
            int row = mt*16 + gid;
            int col = pb0 + warp*64 + nt*8 + tg*2;
            size_t o0 = vbase + (size_t)row*NPIX + col;
            size_t o1 = o0 + (size_t)8*NPIX;
            *(__nv_bfloat162*)&g_ov[o0] = __floats2bfloat162_rn(acc[mt][nt][0], acc[mt][nt][1]);
            *(__nv_bfloat162*)&g_ov[o1] = __floats2bfloat162_rn(acc[mt][nt][2], acc[mt][nt][3]);
        }
}

// ---------------- K6: LN2 -> bf16 into g_xn (register-cached) ----------------
__global__ void __launch_bounds__(256) k_ln2(const float* __restrict__ w,
                                             const float* __restrict__ bia)
{
    const int blk = blockIdx.x;
    const int b  = blk >> 7;
    const int pt = (blk & 127) * 32;
    const int tid = threadIdx.x;
    const int p = tid & 31;
    const int part = tid >> 5;
    const size_t base = (size_t)b*C_*NPIX + pt + p;

    __shared__ float ss[8][32], qq[8][32], s_mu[32], s_is[32];
    float v[32];
    float s = 0.f, sq = 0.f;
    #pragma unroll 8
    for (int j = 0; j < 32; j++) {
        v[j] = g_x1[base + (size_t)(part*32 + j)*NPIX];
        s += v[j]; sq += v[j]*v[j];
    }
    ss[part][p] = s; qq[part][p] = sq;
    __syncthreads();
    if (tid < 32) {
        float a = 0.f, c2 = 0.f;
        #pragma unroll
        for (int j = 0; j < 8; j++) { a += ss[j][tid]; c2 += qq[j][tid]; }
        float mu = a * (1.f/256.f);
        float var = c2 * (1.f/256.f) - mu*mu;
        s_mu[tid] = mu; s_is[tid] = rsqrtf(var + 1e-5f);
    }
    __syncthreads();
    float mu = s_mu[p], is = s_is[p];
    #pragma unroll 8
    for (int j = 0; j < 32; j++) {
        int c = part*32 + j;
        g_xn[base + (size_t)c*NPIX] = __float2bfloat16((v[j] - mu)*is*w[c] + bia[c]);
    }
}

// ---------------- tensor-core GEMM: K=32 chunks, 5-stage pipeline ----------------
template<int MODE>
__global__ void __launch_bounds__(256) k_mma(const __nv_bfloat16* __restrict__ Wb,
                                             const __nv_bfloat16* __restrict__ Act,
                                             const float* __restrict__ res,
                                             float* __restrict__ outp)
{
    constexpr int O = (MODE == 1) ? 1360 : 256;
    constexpr int K = (MODE == 2) ? 680 : 256;
    constexpr int NC = (K + 31) / 32;
    constexpr int ASZ = 128*40;
    constexpr int BSZ = 32*136;
    constexpr int NSTG = 5;

    const int b  = blockIdx.z;
    const int bn = blockIdx.x * 128;
    const int bm = blockIdx.y * 128;
    const int tid = threadIdx.x, lane = tid & 31, warp = tid >> 5;
    const int wm = warp >> 1, wn = warp & 1;
    const int gid = lane >> 2, tg = lane & 3;

    __shared__ __align__(16) __nv_bfloat16 sA[NSTG][ASZ];
    __shared__ __align__(16) __nv_bfloat16 sB[NSTG][BSZ];
    const unsigned sAu = (unsigned)__cvta_generic_to_shared(&sA[0][0]);
    const unsigned sBu = (unsigned)__cvta_generic_to_shared(&sB[0][0]);

    const int ar = tid >> 1, ac = (tid & 1) * 16;
    const int bk = tid >> 3, bn8 = (tid & 7) * 16;
    int arow = bm + ar; if (arow > O-1) arow = O-1;
    const __nv_bfloat16* Arow = Wb + (size_t)arow * K;
    const __nv_bfloat16* Bbase = Act + (size_t)b * K * NPIX + bn;

    float acc[2][8][4];
    #pragma unroll
    for (int i = 0; i < 2; i++)
        #pragma unroll
        for (int j = 0; j < 8; j++)
            #pragma unroll
            for (int q = 0; q < 4; q++) acc[i][j][q] = 0.f;

    auto load_chunk = [&](int c, int buf) {
        const int k0 = c * 32;
        #pragma unroll
        for (int j = 0; j < 2; j++) {
            int ko = ac + j*8;
            unsigned dst = sAu + (buf*ASZ + ar*40 + ko) * 2;
            if (k0 + ko < K) { CP16A(dst, Arow + k0 + ko); }
            else *(float4*)(&sA[buf][ar*40 + ko]) = make_float4(0,0,0,0);
        }
        #pragma unroll
        for (int j = 0; j < 2; j++) {
            int no = bn8 + j*8;
            unsigned dst = sBu + (buf*BSZ + bk*136 + no) * 2;
            if (k0 + bk < K) { CP16(dst, Bbase + (size_t)(k0 + bk)*NPIX + no); }
            else *(float4*)(&sB[buf][bk*136 + no]) = make_float4(0,0,0,0);
        }
        asm volatile("cp.async.commit_group;" ::);
    };

    load_chunk(0, 0);
    load_chunk(1, 1);
    load_chunk(2, 2);
    load_chunk(3, 3);

    int buf = 0;
    for (int c = 0; c < NC; c++) {
        const int rem = NC - 1 - c;
        if (rem >= 3)      { asm volatile("cp.async.wait_group 3;" ::); }
        else if (rem == 2) { asm volatile("cp.async.wait_group 2;" ::); }
        else if (rem == 1) { asm volatile("cp.async.wait_group 1;" ::); }
        else               { asm volatile("cp.async.wait_group 0;" ::); }
        __syncthreads();
        if (c + 4 < NC) {
            int nb = buf + 4; if (nb >= NSTG) nb -= NSTG;
            load_chunk(c + 4, nb);
        }

        #pragma unroll
        for (int kt = 0; kt < 2; kt++) {
            unsigned a[2][4];
            #pragma unroll
            for (int mt = 0; mt < 2; mt++) {
                unsigned addr = sAu + (buf*ASZ +
                    (wm*32 + mt*16 + (lane & 15))*40 + kt*16 + (lane >> 4)*8) * 2;
                LDSM4(a[mt][0], a[mt][1], a[mt][2], a[mt][3], addr);
            }
            #pragma unroll
            for (int ntp = 0; ntp < 4; ntp++) {
                unsigned b0, b1, b2, b3;
                unsigned addr = sBu + (buf*BSZ +
                    (kt*16 + (lane & 7) + ((lane >> 3) & 1)*8)*136 +
                    wn*64 + ntp*16 + (lane >> 4)*8) * 2;
                LDSM4T(b0, b1, b2, b3, addr);
                MMA16816(acc[0][2*ntp],   a[0], b0, b1);
                MMA16816(acc[1][2*ntp],   a[1], b0, b1);
                MMA16816(acc[0][2*ntp+1], a[0], b2, b3);
                MMA16816(acc[1][2*ntp+1], a[1], b2, b3);
            }
        }
        if (++buf == NSTG) buf = 0;
    }

    #pragma unroll
    for (int mt = 0; mt < 2; mt++) {
        #pragma unroll
        for (int nt = 0; nt < 8; nt++) {
            int row = bm + wm*32 + mt*16 + gid;
            int col = bn + wn*64 + nt*8 + tg*2;
            float* a4 = acc[mt][nt];
            if (MODE == 0) {
                size_t o0 = ((size_t)b*256 + row)*NPIX + col;
                size_t o1 = o0 + (size_t)8*NPIX;
                float2 r0 = *(const float2*)&res[o0];
                float2 r1 = *(const float2*)&res[o1];
                *(float2*)&g_x1[o0] = make_float2(r0.x + a4[0], r0.y + a4[1]);
                *(float2*)&g_x1[o1] = make_float2(r1.x + a4[2], r1.y + a4[3]);
            } else if (MODE == 1) {
                if (row < 1360) {
                    size_t o0 = ((size_t)b*1360 + row)*NPIX + col;
                    *(__nv_bfloat162*)&g_t[o0] = __floats2bfloat162_rn(a4[0], a4[1]);
                }
                if (row + 8 < 1360) {
                    size_t o1 = ((size_t)b*1360 + row + 8)*NPIX + col;
                    *(__nv_bfloat162*)&g_t[o1] = __floats2bfloat162_rn(a4[2], a4[3]);
                }
            } else {
                size_t o0 = ((size_t)b*256 + row)*NPIX + col;
                size_t o1 = o0 + (size_t)8*NPIX;
                float2 r0 = *(const float2*)&g_x1[o0];
                float2 r1 = *(const float2*)&g_x1[o1];
                *(float2*)&outp[o0] = make_float2(r0.x + a4[0], r0.y + a4[1]);
                *(float2*)&outp[o1] = make_float2(r1.x + a4[2], r1.y + a4[3]);
            }
        }
    }
}

// ---------------- K8: depthwise + GELU gate (vectorized) ----------------
__global__ void __launch_bounds__(256) k_gate(const float* __restrict__ dw)
{
    const int blk = blockIdx.x;
    const int b = blk / HID_, i = blk % HID_;
    const int tid = threadIdx.x;
    __shared__ __align__(16) __nv_bfloat16 s1[66*SROW];
    __shared__ __align__(16) __nv_bfloat16 s2[66*SROW];

    for (int j = tid; j < 1320; j += 256) {
        if (j < 660) *((float4*)s1 + j) = make_float4(0,0,0,0);
        else         *((float4*)s2 + (j - 660)) = make_float4(0,0,0,0);
    }
    __syncthreads();
    const size_t base1 = ((size_t)b*2*HID_ + i) * NPIX;
    const size_t base2 = ((size_t)b*2*HID_ + HID_ + i) * NPIX;
    #pragma unroll
    for (int g = 0; g < 2; g++) {
        int gi = g*256 + tid;
        int r = gi >> 3, w = (gi & 7) * 8;
        *(float4*)&s1[(r+1)*SROW + 8 + w] = *(const float4*)&g_t[base1 + r*64 + w];
        *(float4*)&s2[(r+1)*SROW + 8 + w] = *(const float4*)&g_t[base2 + r*64 + w];
    }
    __syncthreads();

    float w1[9], w2[9];
    #pragma unroll
    for (int j = 0; j < 9; j++) {
        w1[j] = dw[i*9 + j];
        w2[j] = dw[(HID_ + i)*9 + j];
    }
    const size_t obase = ((size_t)b*HID_ + i) * NPIX;
    #pragma unroll
    for (int g = 0; g < 2; g++) {
        int gi = g*256 + tid;
        int r = gi >> 3, w = (gi & 7) * 8;
        uint4 ho;
        unsigned* hp = &ho.x;
        float hv[2];
        #pragma unroll
        for (int px = 0; px < 8; px++) {
            int s0 = r*SROW + 7 + w + px;
            float a = 0.f, gg = 0.f;
            #pragma unroll
            for (int dy = 0; dy < 3; dy++)
                #pragma unroll
                for (int dx = 0; dx < 3; dx++) {
                    int t = dy*3 + dx;
                    a  = fmaf(__bfloat162float(s1[s0 + dy*SROW + dx]), w1[t], a);
                    gg = fmaf(__bfloat162float(s2[s0 + dy*SROW + dx]), w2[t], gg);
                }
            float ge = 0.5f * a * (1.f + erff(a * 0.70710678118654752f));
            hv[px & 1] = ge * gg;
            if (px & 1) hp[px >> 1] = packbf2(hv[0], hv[1]);
        }
        *(uint4*)&g_h[obase + r*64 + w] = ho;
    }
}

// ---------------- launch ----------------
extern "C" void kernel_launch(void* const* d_in, const int* in_sizes, int n_in,
                              void* d_out, int out_size)
{
    const float* x        = (const float*)d_in[0];
    const float* y        = (const float*)d_in[1];
    const float* ln1x_w   = (const float*)d_in[2];
    const float* ln1x_b   = (const float*)d_in[3];
    const float* ln1y_w   = (const float*)d_in[4];
    const float* ln1y_b   = (const float*)d_in[5];
    const float* ln2_w    = (const float*)d_in[6];
    const float* ln2_b    = (const float*)d_in[7];
    const float* temp     = (const float*)d_in[8];
    const float* qkv_dw   = (const float*)d_in[9];
    const float* proj_w   = (const float*)d_in[10];
    const float* ffn_in_w = (const float*)d_in[11];
    const float* ffn_dw   = (const float*)d_in[12];
    const float* ffn_out_w= (const float*)d_in[13];
    float* out = (float*)d_out;

    __nv_bfloat16 *wP, *wI, *wO;
    cudaGetSymbolAddress((void**)&wP, g_wP);
    cudaGetSymbolAddress((void**)&wI, g_wI);
    cudaGetSymbolAddress((void**)&wO, g_wO);
    __nv_bfloat16 *ov, *xn, *hh;
    cudaGetSymbolAddress((void**)&ov, g_ov);
    cudaGetSymbolAddress((void**)&xn, g_xn);
    cudaGetSymbolAddress((void**)&hh, g_h);

    k_cvtw<<<576, 256>>>(proj_w, ffn_in_w, ffn_out_w);
    k_ln1<<<B_*128, 256>>>(x, y, ln1x_w, ln1x_b, ln1y_w, ln1y_b);
    k_qkv<<<B_*C_, 256>>>(qkv_dw);
    k_qks<<<dim3(16, 64), 256>>>();
    k_soft<<<64, 256>>>(temp);
    k_av2<<<dim3(8, 64), 256>>>();
    k_mma<0><<<dim3(32, 2, B_), 256>>>(wP, ov, x, nullptr);
    k_ln2<<<B_*128, 256>>>(ln2_w, ln2_b);
    k_mma<1><<<dim3(32, 11, B_), 256>>>(wI, xn, nullptr, nullptr);
    k_gate<<<B_*HID_, 256>>>(ffn_dw);
    k_mma<2><<<dim3(32, 2, B_), 256>>>(wO, hh, nullptr, out);
}

// round 14
// speedup vs baseline: 1.1216x; 1.0581x over previous
#include <cuda_runtime.h>
#include <cuda_bf16.h>
#include <math.h>

#define B_ 8
#define C_ 256
#define NPIX 4096
#define HID_ 680
#define SROW 80   // smem plane row stride (bf16), data starts at col 8

// ---------------- scratch ----------------
__device__ __nv_bfloat16 g_xn[B_*C_*NPIX];
__device__ __nv_bfloat16 g_yn[B_*C_*NPIX];
__device__ __nv_bfloat16 g_q [B_*C_*NPIX];
__device__ __nv_bfloat16 g_k [B_*C_*NPIX];
__device__ __nv_bfloat16 g_v [B_*C_*NPIX];
__device__ __nv_bfloat16 g_ov[B_*C_*NPIX];
__device__ float g_x1[B_*C_*NPIX];
__device__ float g_sumsq_q[B_*C_];
__device__ float g_sumsq_k[B_*C_];
__device__ float g_part[16*64*1024];         // split-K partials [seg][bh][c][d]
__device__ __nv_bfloat16 g_attnb[64*1024];
__device__ __nv_bfloat16 g_t[B_*2*HID_*NPIX];
__device__ __nv_bfloat16 g_h[B_*HID_*NPIX];
__device__ __nv_bfloat16 g_wP[256*256];
__device__ __nv_bfloat16 g_wI[1360*256];
__device__ __nv_bfloat16 g_wO[256*680];

// ---------------- mma helpers ----------------
#define MMA16816(d, a, b0, b1) \
    asm volatile("mma.sync.aligned.m16n8k16.row.col.f32.bf16.bf16.f32 " \
        "{%0,%1,%2,%3},{%4,%5,%6,%7},{%8,%9},{%0,%1,%2,%3};" \
        : "+f"(d[0]),"+f"(d[1]),"+f"(d[2]),"+f"(d[3]) \
        : "r"(a[0]),"r"(a[1]),"r"(a[2]),"r"(a[3]),"r"(b0),"r"(b1))

#define LDSM4(r0,r1,r2,r3,addr) \
    asm volatile("ldmatrix.sync.aligned.m8n8.x4.shared.b16 {%0,%1,%2,%3},[%4];" \
        : "=r"(r0),"=r"(r1),"=r"(r2),"=r"(r3) : "r"(addr))

#define LDSM4T(r0,r1,r2,r3,addr) \
    asm volatile("ldmatrix.sync.aligned.m8n8.x4.trans.shared.b16 {%0,%1,%2,%3},[%4];" \
        : "=r"(r0),"=r"(r1),"=r"(r2),"=r"(r3) : "r"(addr))

#define CP16(dst, src) \
    asm volatile("cp.async.cg.shared.global [%0], [%1], 16;" :: "r"(dst), "l"(src))

#define CP16A(dst, src) \
    asm volatile("cp.async.ca.shared.global [%0], [%1], 16;" :: "r"(dst), "l"(src))

__device__ __forceinline__ unsigned packbf2(float a, float b) {
    __nv_bfloat162 h = __floats2bfloat162_rn(a, b);
    return *reinterpret_cast<unsigned*>(&h);
}

// load 12-bf16 window (cols c0..c0+11, c0 even) from smem row into floats
__device__ __forceinline__ void ldwin12(const __nv_bfloat16* row, int c0, float* o) {
    #pragma unroll
    for (int u = 0; u < 6; u++) {
        __nv_bfloat162 h2 = *reinterpret_cast<const __nv_bfloat162*>(&row[c0 + u*2]);
        o[u*2]   = __bfloat162float(h2.x);
        o[u*2+1] = __bfloat162float(h2.y);
    }
}

// ---------------- weight convert ----------------
__global__ void k_cvtw(const float* __restrict__ p, const float* __restrict__ wi,
                       const float* __restrict__ wo)
{
    const int NP = 256*256, NI = 1360*256, NO = 256*680;
    for (int i = blockIdx.x*256 + threadIdx.x; i < NP+NI+NO; i += gridDim.x*256) {
        if (i < NP) g_wP[i] = __float2bfloat16(p[i]);
        else if (i < NP+NI) g_wI[i-NP] = __float2bfloat16(wi[i-NP]);
        else g_wO[i-NP-NI] = __float2bfloat16(wo[i-NP-NI]);
    }
}

// ---------------- K1: LayerNorm x,y (register-cached) ----------------
__global__ void __launch_bounds__(256) k_ln1(
    const float* __restrict__ x, const float* __restrict__ y,
    const float* __restrict__ xw, const float* __restrict__ xb,
    const float* __restrict__ yw, const float* __restrict__ yb)
{
    const int blk = blockIdx.x;
    const int b   = blk >> 7;
    const int pt  = (blk & 127) * 32;
    const int tid = threadIdx.x;
    const int p    = tid & 31;
    const int part = tid >> 5;
    const size_t base = (size_t)b*C_*NPIX + pt + p;

    __shared__ float s_s[8][32], s_q[8][32], s_mu[32], s_is[32];
    float v[32];

    {
        float s = 0.f, sq = 0.f;
        #pragma unroll 8
        for (int j = 0; j < 32; j++) {
            v[j] = x[base + (size_t)(part*32 + j)*NPIX];
            s += v[j]; sq += v[j]*v[j];
        }
        s_s[part][p] = s; s_q[part][p] = sq;
        __syncthreads();
        if (tid < 32) {
            float a = 0.f, c2 = 0.f;
            #pragma unroll
            for (int j = 0; j < 8; j++) { a += s_s[j][tid]; c2 += s_q[j][tid]; }
            float mu = a * (1.f/256.f);
            float var = c2 * (1.f/256.f) - mu*mu;
            s_mu[tid] = mu; s_is[tid] = rsqrtf(var + 1e-5f);
        }
        __syncthreads();
        float mu = s_mu[p], is = s_is[p];
        #pragma unroll 8
        for (int j = 0; j < 32; j++) {
            int c = part*32 + j;
            g_xn[base + (size_t)c*NPIX] = __float2bfloat16((v[j] - mu)*is*xw[c] + xb[c]);
        }
    }
    __syncthreads();
    {
        float s = 0.f, sq = 0.f;
        #pragma unroll 8
        for (int j = 0; j < 32; j++) {
            v[j] = y[base + (size_t)(part*32 + j)*NPIX];
            s += v[j]; sq += v[j]*v[j];
        }
        s_s[part][p] = s; s_q[part][p] = sq;
        __syncthreads();
        if (tid < 32) {
            float a = 0.f, c2 = 0.f;
            #pragma unroll
            for (int j = 0; j < 8; j++) { a += s_s[j][tid]; c2 += s_q[j][tid]; }
            float mu = a * (1.f/256.f);
            float var = c2 * (1.f/256.f) - mu*mu;
            s_mu[tid] = mu; s_is[tid] = rsqrtf(var + 1e-5f);
        }
        __syncthreads();
        float mu = s_mu[p], is = s_is[p];
        #pragma unroll 8
        for (int j = 0; j < 32; j++) {
            int c = part*32 + j;
            g_yn[base + (size_t)c*NPIX] = __float2bfloat16((v[j] - mu)*is*yw[c] + yb[c]);
        }
    }
}

// ---------------- K2: depthwise QKV + sumsq (windowed LDS) ----------------
__global__ void __launch_bounds__(256) k_qkv(const float* __restrict__ dw)
{
    const int blk = blockIdx.x;
    const int c   = blk & 255;
    const int tid = threadIdx.x;
    __shared__ __align__(16) __nv_bfloat16 sx[66*SROW];
    __shared__ __align__(16) __nv_bfloat16 sy[66*SROW];

    for (int i = tid; i < 1320; i += 256) {
        if (i < 660) *((float4*)sx + i) = make_float4(0,0,0,0);
        else         *((float4*)sy + (i - 660)) = make_float4(0,0,0,0);
    }
    __syncthreads();
    const size_t pbase = (size_t)blk * NPIX;
    #pragma unroll
    for (int g = 0; g < 2; g++) {
        int gi = g*256 + tid;
        int r = gi >> 3, w = (gi & 7) * 8;
        *(float4*)&sx[(r+1)*SROW + 8 + w] = *(const float4*)&g_xn[pbase + r*64 + w];
        *(float4*)&sy[(r+1)*SROW + 8 + w] = *(const float4*)&g_yn[pbase + r*64 + w];
    }
    __syncthreads();

    float wq[9], wk[9], wv[9];
    #pragma unroll
    for (int j = 0; j < 9; j++) {
        wq[j] = dw[c*9 + j];
        wk[j] = dw[(256 + c)*9 + j];
        wv[j] = dw[(512 + c)*9 + j];
    }

    float sqq = 0.f, sqk = 0.f;
    #pragma unroll
    for (int g = 0; g < 2; g++) {
        int gi = g*256 + tid;
        int r = gi >> 3, w = (gi & 7) * 8;
        const int c0 = 6 + w;          // window cols c0..c0+11 (even start)
        uint4 qo, ko, vo;
        unsigned* qp = &qo.x; unsigned* kp = &ko.x; unsigned* vp = &vo.x;

        // ----- plane x -> q -----
        float qa[8];
        {
            float win[3][12];
            #pragma unroll
            for (int dy = 0; dy < 3; dy++)
                ldwin12(&sx[(r+dy)*SROW], c0, win[dy]);
            #pragma unroll
            for (int i = 0; i < 8; i++) {
                float q = 0.f;
                #pragma unroll
                for (int dy = 0; dy < 3; dy++)
                    #pragma unroll
                    for (int dx = 0; dx < 3; dx++)
                        q = fmaf(win[dy][1 + i + dx], wq[dy*3 + dx], q);
                qa[i] = q;
                sqq += q*q;
            }
        }
        // ----- plane y -> k, v -----
        float ka[8], va[8];
        {
            float win[3][12];
            #pragma unroll
            for (int dy = 0; dy < 3; dy++)
                ldwin12(&sy[(r+dy)*SROW], c0, win[dy]);
            #pragma unroll
            for (int i = 0; i < 8; i++) {
                float k = 0.f, v = 0.f;
                #pragma unroll
                for (int dy = 0; dy < 3; dy++)
                    #pragma unroll
                    for (int dx = 0; dx < 3; dx++) {
                        float yv = win[dy][1 + i + dx];
                        int t = dy*3 + dx;
                        k = fmaf(yv, wk[t], k);
                        v = fmaf(yv, wv[t], v);
                    }
                ka[i] = k; va[i] = v;
                sqk += k*k;
            }
        }
        #pragma unroll
        for (int i = 0; i < 4; i++) {
            qp[i] = packbf2(qa[2*i], qa[2*i+1]);
            kp[i] = packbf2(ka[2*i], ka[2*i+1]);
            vp[i] = packbf2(va[2*i], va[2*i+1]);
        }
        *(uint4*)&g_q[pbase + r*64 + w] = qo;
        *(uint4*)&g_k[pbase + r*64 + w] = ko;
        *(uint4*)&g_v[pbase + r*64 + w] = vo;
    }
    #pragma unroll
    for (int off = 16; off; off >>= 1) {
        sqq += __shfl_down_sync(0xffffffffu, sqq, off);
        sqk += __shfl_down_sync(0xffffffffu, sqk, off);
    }
    __shared__ float rq[8], rk[8];
    if ((tid & 31) == 0) { rq[tid >> 5] = sqq; rk[tid >> 5] = sqk; }
    __syncthreads();
    if (tid == 0) {
        float a = 0.f, bqv = 0.f;
        #pragma unroll
        for (int j = 0; j < 8; j++) { a += rq[j]; bqv += rk[j]; }
        g_sumsq_q[blk] = a;
        g_sumsq_k[blk] = bqv;
    }
}

// ---------------- K3: QK^T partials (split-K=16, mma) ----------------
__global__ void __launch_bounds__(256) k_qks()
{
    const int seg = blockIdx.x;   // 0..15 (256 pixels each)
    const int bh  = blockIdx.y;   // 0..63
    const int b = bh >> 3, h = bh & 7;
    const int tid = threadIdx.x, lane = tid & 31, warp = tid >> 5;
    const int gid = lane >> 2, tg = lane & 3;

    __shared__ __align__(16) char smraw[2*2*32*136*2];
    __nv_bfloat16* sQ = (__nv_bfloat16*)smraw;
    __nv_bfloat16* sK = sQ + 2*32*136;
    float* stage = (float*)smraw;
    const unsigned sQu = (unsigned)__cvta_generic_to_shared(sQ);
    const unsigned sKu = (unsigned)__cvta_generic_to_shared(sK);

    const size_t base = ((size_t)b*C_ + h*32) * NPIX;
    const int r  = tid >> 3;
    const int cg = (tid & 7) * 16;

    auto prefetch = [&](int c, int buf) {
        const int n0 = seg*256 + c * 128;
        const __nv_bfloat16* qp = g_q + base + (size_t)r*NPIX + n0 + cg;
        const __nv_bfloat16* kp = g_k + base + (size_t)r*NPIX + n0 + cg;
        unsigned dq = sQu + (buf*32*136 + r*136 + cg) * 2;
        unsigned dk = sKu + (buf*32*136 + r*136 + cg) * 2;
        CP16(dq,      qp);
        CP16(dq + 16, qp + 8);
        CP16(dk,      kp);
        CP16(dk + 16, kp + 8);
        asm volatile("cp.async.commit_group;" ::);
    };

    float acc[2][4][4];
    #pragma unroll
    for (int i = 0; i < 2; i++)
        #pragma unroll
        for (int j = 0; j < 4; j++)
            #pragma unroll
            for (int q = 0; q < 4; q++) acc[i][j][q] = 0.f;

    prefetch(0, 0);
    prefetch(1, 1);

    #pragma unroll
    for (int c = 0; c < 2; c++) {
        const int buf = c;
        if (c == 0) { asm volatile("cp.async.wait_group 1;" ::); }
        else        { asm volatile("cp.async.wait_group 0;" ::); }
        __syncthreads();

        const int col = warp*16 + (lane >> 4)*8;
        unsigned a[2][4];
        #pragma unroll
        for (int mt = 0; mt < 2; mt++) {
            unsigned addr = sQu + (buf*32*136 + (mt*16 + (lane & 15))*136 + col) * 2;
            LDSM4(a[mt][0], a[mt][1], a[mt][2], a[mt][3], addr);
        }
        #pragma unroll
        for (int nt = 0; nt < 2; nt++) {
            unsigned r0, r1, r2, r3;
            unsigned addr = sKu + (buf*32*136 + (nt*16 + (lane & 15))*136 + col) * 2;
            LDSM4(r0, r1, r2, r3, addr);
            MMA16816(acc[0][nt*2],   a[0], r0, r2);
            MMA16816(acc[1][nt*2],   a[1], r0, r2);
            MMA16816(acc[0][nt*2+1], a[0], r1, r3);
            MMA16816(acc[1][nt*2+1], a[1], r1, r3);
        }
        __syncthreads();
    }

    #pragma unroll
    for (int mt = 0; mt < 2; mt++)
        #pragma unroll
        for (int j = 0; j < 4; j++) {
            int c0 = mt*16 + gid, d0 = j*8 + tg*2;
            stage[warp*1056 + c0*33 + d0]       = acc[mt][j][0];
            stage[warp*1056 + c0*33 + d0 + 1]   = acc[mt][j][1];
            stage[warp*1056 + (c0+8)*33 + d0]   = acc[mt][j][2];
            stage[warp*1056 + (c0+8)*33 + d0+1] = acc[mt][j][3];
        }
    __syncthreads();

    const int cc = tid >> 3;
    const int dg = (tid & 7) * 4;
    float4 v = make_float4(0.f, 0.f, 0.f, 0.f);
    #pragma unroll
    for (int w = 0; w < 8; w++) {
        const float* sp = &stage[w*1056 + cc*33 + dg];
        v.x += sp[0]; v.y += sp[1]; v.z += sp[2]; v.w += sp[3];
    }
    *(float4*)&g_part[(((size_t)seg*64 + bh)*32 + cc)*32 + dg] = v;
}

// ---------------- K4: reduce partials + scale + softmax ----------------
__global__ void __launch_bounds__(256) k_soft(const float* __restrict__ temp)
{
    const int bh = blockIdx.x;
    const int b = bh >> 3, h = bh & 7;
    const int tid = threadIdx.x;
    const int cc = tid >> 3;
    const int dg = (tid & 7) * 4;
    const float t = temp[h];

    float v[4] = {0.f, 0.f, 0.f, 0.f};
    #pragma unroll
    for (int sg = 0; sg < 16; sg++) {
        float4 l = *(const float4*)&g_part[(((size_t)sg*64 + bh)*32 + cc)*32 + dg];
        v[0] += l.x; v[1] += l.y; v[2] += l.z; v[3] += l.w;
    }
    float nq = sqrtf(g_sumsq_q[b*C_ + h*32 + cc]);
    float rq = 1.f / fmaxf(nq, 1e-12f);
    float mx = -1e30f;
    #pragma unroll
    for (int j = 0; j < 4; j++) {
        float nk = sqrtf(g_sumsq_k[b*C_ + h*32 + dg + j]);
        v[j] *= rq * (1.f / fmaxf(nk, 1e-12f)) * t;
        mx = fmaxf(mx, v[j]);
    }
    #pragma unroll
    for (int m = 1; m < 8; m <<= 1) mx = fmaxf(mx, __shfl_xor_sync(0xffffffffu, mx, m));
    float sum = 0.f;
    #pragma unroll
    for (int j = 0; j < 4; j++) { v[j] = expf(v[j] - mx); sum += v[j]; }
    #pragma unroll
    for (int m = 1; m < 8; m <<= 1) sum += __shfl_xor_sync(0xffffffffu, sum, m);
    float inv = 1.f / sum;
    __nv_bfloat162* op = reinterpret_cast<__nv_bfloat162*>(&g_attnb[(size_t)bh*1024 + cc*32 + dg]);
    op[0] = __floats2bfloat162_rn(v[0]*inv, v[1]*inv);
    op[1] = __floats2bfloat162_rn(v[2]*inv, v[3]*inv);
}

// ---------------- K5: out = attn @ v (mma) ----------------
__global__ void __launch_bounds__(256) k_av2()
{
    const int seg = blockIdx.x;
    const int bh  = blockIdx.y;
    const int b = bh >> 3, h = bh & 7;
    const int tid = threadIdx.x, lane = tid & 31, warp = tid >> 5;
    const int gid = lane >> 2, tg = lane & 3;

    __shared__ __align__(16) __nv_bfloat16 sA[32*40];
    __shared__ __align__(16) __nv_bfloat16 sV[32*520];
    const unsigned sAu = (unsigned)__cvta_generic_to_shared(&sA[0]);
    const unsigned sVu = (unsigned)__cvta_generic_to_shared(&sV[0]);

    {
        int c0 = tid >> 3, d0 = (tid & 7) * 4;
        const __nv_bfloat162* ap = reinterpret_cast<const __nv_bfloat162*>(
            &g_attnb[(size_t)bh*1024 + c0*32 + d0]);
        __nv_bfloat162* sp = reinterpret_cast<__nv_bfloat162*>(&sA[c0*40 + d0]);
        sp[0] = ap[0]; sp[1] = ap[1];
    }
    const size_t vbase = ((size_t)b*C_ + h*32) * NPIX;
    const int pb0 = seg * 512;
    {
        int r = tid >> 3, cg = (tid & 7) * 64;
        #pragma unroll
        for (int j = 0; j < 8; j++)
            *(float4*)&sV[r*520 + cg + j*8] =
                *(const float4*)&g_v[vbase + (size_t)r*NPIX + pb0 + cg + j*8];
    }
    __syncthreads();

    float acc[2][8][4];
    #pragma unroll
    for (int i = 0; i < 2; i++)
        #pragma unroll
        for (int j = 0; j < 8; j++)
            #pragma unroll
            for (int q = 0; q < 4; q++) acc[i][j][q] = 0.f;

    #pragma unroll
    for (int kt = 0; kt < 2; kt++) {
        unsigned a[2][4];
        #pragma unroll
        for (int mt = 0; mt < 2; mt++) {
            unsigned addr = sAu + ((mt*16 + (lane & 15))*40 + kt*16 + (lane >> 4)*8) * 2;
            LDSM4(a[mt][0], a[mt][1], a[mt][2], a[mt][3], addr);
        }
        #pragma unroll
        for (int ntp = 0; ntp < 4; ntp++) {
            unsigned b0, b1, b2, b3;
            unsigned addr = sVu + ((kt*16 + (lane & 7) + ((lane >> 3) & 1)*8)*520 +
                warp*64 + ntp*16 + (lane >> 4)*8) * 2;
            LDSM4T(b0, b1, b2, b3, addr);
            MMA16816(acc[0][2*ntp],   a[0], b0, b1);
            MMA16816(acc[1][2*ntp],   a[1], b0, b1);
            MMA16816(acc[0][2*ntp+1], a[0], b2, b3);
            MMA16816(acc[1][2*ntp+1], a[1], b2, b3);
        }
    }

    #pragma unroll
    for (int mt = 0; mt < 2; mt++)
        #pragma unroll
        for (int nt = 0; nt < 8; nt++) {
            int row = mt*16 + gid;
            int col = pb0 + warp*64 + nt*8 + tg*2;
            size_t o0 = vbase + (size_t)row*NPIX + col;
            size_t o1 = o0 + (size_t)8*NPIX;
            *(__nv_bfloat162*)&g_ov[o0] = __floats2bfloat162_rn(acc[mt][nt][0], acc[mt][nt][1]);
            *(__nv_bfloat162*)&g_ov[o1] = __floats2bfloat162_rn(acc[mt][nt][2], acc[mt][nt][3]);
        }
}

// ---------------- K6: LN2 -> bf16 into g_xn (register-cached) ----------------
__global__ void __launch_bounds__(256) k_ln2(const float* __restrict__ w,
                                             const float* __restrict__ bia)
{
    const int blk = blockIdx.x;
    const int b  = blk >> 7;
    const int pt = (blk & 127) * 32;
    const int tid = threadIdx.x;
    const int p = tid & 31;
    const int part = tid >> 5;
    const size_t base = (size_t)b*C_*NPIX + pt + p;

    __shared__ float ss[8][32], qq[8][32], s_mu[32], s_is[32];
    float v[32];
    float s = 0.f, sq = 0.f;
    #pragma unroll 8
    for (int j = 0; j < 32; j++) {
        v[j] = g_x1[base + (size_t)(part*32 + j)*NPIX];
        s += v[j]; sq += v[j]*v[j];
    }
    ss[part][p] = s; qq[part][p] = sq;
    __syncthreads();
    if (tid < 32) {
        float a = 0.f, c2 = 0.f;
        #pragma unroll
        for (int j = 0; j < 8; j++) { a += ss[j][tid]; c2 += qq[j][tid]; }
        float mu = a * (1.f/256.f);
        float var = c2 * (1.f/256.f) - mu*mu;
        s_mu[tid] = mu; s_is[tid] = rsqrtf(var + 1e-5f);
    }
    __syncthreads();
    float mu = s_mu[p], is = s_is[p];
    #pragma unroll 8
    for (int j = 0; j < 32; j++) {
        int c = part*32 + j;
        g_xn[base + (size_t)c*NPIX] = __float2bfloat16((v[j] - mu)*is*w[c] + bia[c]);
    }
}

// ---------------- tensor-core GEMM: K=32 chunks, 5-stage pipeline ----------------
template<int MODE>
__global__ void __launch_bounds__(256) k_mma(const __nv_bfloat16* __restrict__ Wb,
                                             const __nv_bfloat16* __restrict__ Act,
                                             const float* __restrict__ res,
                                             float* __restrict__ outp)
{
    constexpr int O = (MODE == 1) ? 1360 : 256;
    constexpr int K = (MODE == 2) ? 680 : 256;
    constexpr int NC = (K + 31) / 32;
    constexpr int ASZ = 128*40;
    constexpr int BSZ = 32*136;
    constexpr int NSTG = 5;

    const int b  = blockIdx.z;
    const int bn = blockIdx.x * 128;
    const int bm = blockIdx.y * 128;
    const int tid = threadIdx.x, lane = tid & 31, warp = tid >> 5;
    const int wm = warp >> 1, wn = warp & 1;
    const int gid = lane >> 2, tg = lane & 3;

    __shared__ __align__(16) __nv_bfloat16 sA[NSTG][ASZ];
    __shared__ __align__(16) __nv_bfloat16 sB[NSTG][BSZ];
    const unsigned sAu = (unsigned)__cvta_generic_to_shared(&sA[0][0]);
    const unsigned sBu = (unsigned)__cvta_generic_to_shared(&sB[0][0]);

    const int ar = tid >> 1, ac = (tid & 1) * 16;
    const int bk = tid >> 3, bn8 = (tid & 7) * 16;
    int arow = bm + ar; if (arow > O-1) arow = O-1;
    const __nv_bfloat16* Arow = Wb + (size_t)arow * K;
    const __nv_bfloat16* Bbase = Act + (size_t)b * K * NPIX + bn;

    float acc[2][8][4];
    #pragma unroll
    for (int i = 0; i < 2; i++)
        #pragma unroll
        for (int j = 0; j < 8; j++)
            #pragma unroll
            for (int q = 0; q < 4; q++) acc[i][j][q] = 0.f;

    auto load_chunk = [&](int c, int buf) {
        const int k0 = c * 32;
        #pragma unroll
        for (int j = 0; j < 2; j++) {
            int ko = ac + j*8;
            unsigned dst = sAu + (buf*ASZ + ar*40 + ko) * 2;
            if (k0 + ko < K) { CP16A(dst, Arow + k0 + ko); }
            else *(float4*)(&sA[buf][ar*40 + ko]) = make_float4(0,0,0,0);
        }
        #pragma unroll
        for (int j = 0; j < 2; j++) {
            int no = bn8 + j*8;
            unsigned dst = sBu + (buf*BSZ + bk*136 + no) * 2;
            if (k0 + bk < K) { CP16(dst, Bbase + (size_t)(k0 + bk)*NPIX + no); }
            else *(float4*)(&sB[buf][bk*136 + no]) = make_float4(0,0,0,0);
        }
        asm volatile("cp.async.commit_group;" ::);
    };

    load_chunk(0, 0);
    load_chunk(1, 1);
    load_chunk(2, 2);
    load_chunk(3, 3);

    int buf = 0;
    for (int c = 0; c < NC; c++) {
        const int rem = NC - 1 - c;
        if (rem >= 3)      { asm volatile("cp.async.wait_group 3;" ::); }
        else if (rem == 2) { asm volatile("cp.async.wait_group 2;" ::); }
        else if (rem == 1) { asm volatile("cp.async.wait_group 1;" ::); }
        else               { asm volatile("cp.async.wait_group 0;" ::); }
        __syncthreads();
        if (c + 4 < NC) {
            int nb = buf + 4; if (nb >= NSTG) nb -= NSTG;
            load_chunk(c + 4, nb);
        }

        #pragma unroll
        for (int kt = 0; kt < 2; kt++) {
            unsigned a[2][4];
            #pragma unroll
            for (int mt = 0; mt < 2; mt++) {
                unsigned addr = sAu + (buf*ASZ +
                    (wm*32 + mt*16 + (lane & 15))*40 + kt*16 + (lane >> 4)*8) * 2;
                LDSM4(a[mt][0], a[mt][1], a[mt][2], a[mt][3], addr);
            }
            #pragma unroll
            for (int ntp = 0; ntp < 4; ntp++) {
                unsigned b0, b1, b2, b3;
                unsigned addr = sBu + (buf*BSZ +
                    (kt*16 + (lane & 7) + ((lane >> 3) & 1)*8)*136 +
                    wn*64 + ntp*16 + (lane >> 4)*8) * 2;
                LDSM4T(b0, b1, b2, b3, addr);
                MMA16816(acc[0][2*ntp],   a[0], b0, b1);
                MMA16816(acc[1][2*ntp],   a[1], b0, b1);
                MMA16816(acc[0][2*ntp+1], a[0], b2, b3);
                MMA16816(acc[1][2*ntp+1], a[1], b2, b3);
            }
        }
        if (++buf == NSTG) buf = 0;
    }

    #pragma unroll
    for (int mt = 0; mt < 2; mt++) {
        #pragma unroll
        for (int nt = 0; nt < 8; nt++) {
            int row = bm + wm*32 + mt*16 + gid;
            int col = bn + wn*64 + nt*8 + tg*2;
            float* a4 = acc[mt][nt];
            if (MODE == 0) {
                size_t o0 = ((size_t)b*256 + row)*NPIX + col;
                size_t o1 = o0 + (size_t)8*NPIX;
                float2 r0 = *(const float2*)&res[o0];
                float2 r1 = *(const float2*)&res[o1];
                *(float2*)&g_x1[o0] = make_float2(r0.x + a4[0], r0.y + a4[1]);
                *(float2*)&g_x1[o1] = make_float2(r1.x + a4[2], r1.y + a4[3]);
            } else if (MODE == 1) {
                if (row < 1360) {
                    size_t o0 = ((size_t)b*1360 + row)*NPIX + col;
                    *(__nv_bfloat162*)&g_t[o0] = __floats2bfloat162_rn(a4[0], a4[1]);
                }
                if (row + 8 < 1360) {
                    size_t o1 = ((size_t)b*1360 + row + 8)*NPIX + col;
                    *(__nv_bfloat162*)&g_t[o1] = __floats2bfloat162_rn(a4[2], a4[3]);
                }
            } else {
                size_t o0 = ((size_t)b*256 + row)*NPIX + col;
                size_t o1 = o0 + (size_t)8*NPIX;
                float2 r0 = *(const float2*)&g_x1[o0];
                float2 r1 = *(const float2*)&g_x1[o1];
                *(float2*)&outp[o0] = make_float2(r0.x + a4[0], r0.y + a4[1]);
                *(float2*)&outp[o1] = make_float2(r1.x + a4[2], r1.y + a4[3]);
            }
        }
    }
}

// ---------------- K8: depthwise + GELU gate (windowed LDS) ----------------
__global__ void __launch_bounds__(256) k_gate(const float* __restrict__ dw)
{
    const int blk = blockIdx.x;
    const int b = blk / HID_, i = blk % HID_;
    const int tid = threadIdx.x;
    __shared__ __align__(16) __nv_bfloat16 s1[66*SROW];
    __shared__ __align__(16) __nv_bfloat16 s2[66*SROW];

    for (int j = tid; j < 1320; j += 256) {
        if (j < 660) *((float4*)s1 + j) = make_float4(0,0,0,0);
        else         *((float4*)s2 + (j - 660)) = make_float4(0,0,0,0);
    }
    __syncthreads();
    const size_t base1 = ((size_t)b*2*HID_ + i) * NPIX;
    const size_t base2 = ((size_t)b*2*HID_ + HID_ + i) * NPIX;
    #pragma unroll
    for (int g = 0; g < 2; g++) {
        int gi = g*256 + tid;
        int r = gi >> 3, w = (gi & 7) * 8;
        *(float4*)&s1[(r+1)*SROW + 8 + w] = *(const float4*)&g_t[base1 + r*64 + w];
        *(float4*)&s2[(r+1)*SROW + 8 + w] = *(const float4*)&g_t[base2 + r*64 + w];
    }
    __syncthreads();

    float w1[9], w2[9];
    #pragma unroll
    for (int j = 0; j < 9; j++) {
        w1[j] = dw[i*9 + j];
        w2[j] = dw[(HID_ + i)*9 + j];
    }
    const size_t obase = ((size_t)b*HID_ + i) * NPIX;
    #pragma unroll
    for (int g = 0; g < 2; g++) {
        int gi = g*256 + tid;
        int r = gi >> 3, w = (gi & 7) * 8;
        const int c0 = 6 + w;
        float av[8], gv[8];
        // plane 1 -> a
        {
            float win[3][12];
            #pragma unroll
            for (int dy = 0; dy < 3; dy++)
                ldwin12(&s1[(r+dy)*SROW], c0, win[dy]);
            #pragma unroll
            for (int px = 0; px < 8; px++) {
                float a = 0.f;
                #pragma unroll
                for (int dy = 0; dy < 3; dy++)
                    #pragma unroll
                    for (int dx = 0; dx < 3; dx++)
                        a = fmaf(win[dy][1 + px + dx], w1[dy*3 + dx], a);
                av[px] = a;
            }
        }
        // plane 2 -> g
        {
            float win[3][12];
            #pragma unroll
            for (int dy = 0; dy < 3; dy++)
                ldwin12(&s2[(r+dy)*SROW], c0, win[dy]);
            #pragma unroll
            for (int px = 0; px < 8; px++) {
                float gg = 0.f;
                #pragma unroll
                for (int dy = 0; dy < 3; dy++)
                    #pragma unroll
                    for (int dx = 0; dx < 3; dx++)
                        gg = fmaf(win[dy][1 + px + dx], w2[dy*3 + dx], gg);
                gv[px] = gg;
            }
        }
        uint4 ho;
        unsigned* hp = &ho.x;
        #pragma unroll
        for (int px = 0; px < 4; px++) {
            float a0 = av[2*px],   g0 = gv[2*px];
            float a1 = av[2*px+1], g1 = gv[2*px+1];
            float ge0 = 0.5f * a0 * (1.f + erff(a0 * 0.70710678118654752f));
            float ge1 = 0.5f * a1 * (1.f + erff(a1 * 0.70710678118654752f));
            hp[px] = packbf2(ge0 * g0, ge1 * g1);
        }
        *(uint4*)&g_h[obase + r*64 + w] = ho;
    }
}

// ---------------- launch ----------------
extern "C" void kernel_launch(void* const* d_in, const int* in_sizes, int n_in,
                              void* d_out, int out_size)
{
    const float* x        = (const float*)d_in[0];
    const float* y        = (const float*)d_in[1];
    const float* ln1x_w   = (const float*)d_in[2];
    const float* ln1x_b   = (const float*)d_in[3];
    const float* ln1y_w   = (const float*)d_in[4];
    const float* ln1y_b   = (const float*)d_in[5];
    const float* ln2_w    = (const float*)d_in[6];
    const float* ln2_b    = (const float*)d_in[7];
    const float* temp     = (const float*)d_in[8];
    const float* qkv_dw   = (const float*)d_in[9];
    const float* proj_w   = (const float*)d_in[10];
    const float* ffn_in_w = (const float*)d_in[11];
    const float* ffn_dw   = (const float*)d_in[12];
    const float* ffn_out_w= (const float*)d_in[13];
    float* out = (float*)d_out;

    __nv_bfloat16 *wP, *wI, *wO;
    cudaGetSymbolAddress((void**)&wP, g_wP);
    cudaGetSymbolAddress((void**)&wI, g_wI);
    cudaGetSymbolAddress((void**)&wO, g_wO);
    __nv_bfloat16 *ov, *xn, *hh;
    cudaGetSymbolAddress((void**)&ov, g_ov);
    cudaGetSymbolAddress((void**)&xn, g_xn);
    cudaGetSymbolAddress((void**)&hh, g_h);

    k_cvtw<<<576, 256>>>(proj_w, ffn_in_w, ffn_out_w);
    k_ln1<<<B_*128, 256>>>(x, y, ln1x_w, ln1x_b, ln1y_w, ln1y_b);
    k_qkv<<<B_*C_, 256>>>(qkv_dw);
    k_qks<<<dim3(16, 64), 256>>>();
    k_soft<<<64, 256>>>(temp);
    k_av2<<<dim3(8, 64), 256>>>();
    k_mma<0><<<dim3(32, 2, B_), 256>>>(wP, ov, x, nullptr);
    k_ln2<<<B_*128, 256>>>(ln2_w, ln2_b);
    k_mma<1><<<dim3(32, 11, B_), 256>>>(wI, xn, nullptr, nullptr);
    k_gate<<<B_*HID_, 256>>>(ffn_dw);
    k_mma<2><<<dim3(32, 2, B_), 256>>>(wO, hh, nullptr, out);
}